// round 1
// baseline (speedup 1.0000x reference)
#include <cuda_runtime.h>
#include <math_constants.h>

// ---------------------------------------------------------------------------
// MultiHeadAttention: B=2, S=2048, D=1024, H=16, Hd=64, fp32, causal.
// Phase 1: Q/K/V = X @ W^T        (fused NT-SGEMM, grid.z = {q,k,v})
// Phase 2: flash attention fp32   (per (b,h,qtile) CTA, online softmax)
// Phase 3: out = ctx @ Wo^T + bo  (NT-SGEMM with bias)
// ---------------------------------------------------------------------------

#define B_   2
#define S_   2048
#define D_   1024
#define H_   16
#define HD_  64

#define GBM 128
#define GBN 128
#define GBK 16

// Scratch (allocation-free rule: __device__ globals). 4 x 16 MB.
__device__ float g_Q[B_ * S_ * D_];
__device__ float g_K[B_ * S_ * D_];
__device__ float g_V[B_ * S_ * D_];
__device__ float g_ctx[B_ * S_ * D_];

// ---------------------------------------------------------------------------
// NT SGEMM body: C[M,N] = A[M,K] * B[N,K]^T (+ bias[n])
// 128x128 block tile, BK=16, 256 threads, 8x8 micro-tile per thread.
// ---------------------------------------------------------------------------
__device__ __forceinline__ void gemm_nt_body(const float* __restrict__ A,
                                             const float* __restrict__ Bm,
                                             float* __restrict__ C,
                                             const float* __restrict__ bias,
                                             int M, int N, int K) {
    __shared__ float As[GBK][GBM];
    __shared__ float Bs[GBK][GBN];

    const int tid = threadIdx.x;
    const int tx  = tid & 15;       // 0..15
    const int ty  = tid >> 4;       // 0..15
    const int bm  = blockIdx.y * GBM;
    const int bn  = blockIdx.x * GBN;

    float acc[8][8];
#pragma unroll
    for (int i = 0; i < 8; i++)
#pragma unroll
        for (int j = 0; j < 8; j++) acc[i][j] = 0.f;

    for (int k0 = 0; k0 < K; k0 += GBK) {
        // Load BMxBK of A and BNxBK of B, transposed into smem.
        // 128 rows * 4 float4 per row = 512 float4; 256 threads -> 2 each.
#pragma unroll
        for (int t = 0; t < 2; t++) {
            int idx = tid + t * 256;        // 0..511
            int row = idx >> 2;             // 0..127
            int v   = (idx & 3) << 2;       // 0,4,8,12
            float4 a = *(const float4*)(A + (size_t)(bm + row) * K + k0 + v);
            As[v + 0][row] = a.x; As[v + 1][row] = a.y;
            As[v + 2][row] = a.z; As[v + 3][row] = a.w;
            float4 b = *(const float4*)(Bm + (size_t)(bn + row) * K + k0 + v);
            Bs[v + 0][row] = b.x; Bs[v + 1][row] = b.y;
            Bs[v + 2][row] = b.z; Bs[v + 3][row] = b.w;
        }
        __syncthreads();

#pragma unroll
        for (int kk = 0; kk < GBK; kk++) {
            float ra[8], rb[8];
            *(float4*)(ra)     = *(const float4*)&As[kk][ty * 8];
            *(float4*)(ra + 4) = *(const float4*)&As[kk][ty * 8 + 4];
            *(float4*)(rb)     = *(const float4*)&Bs[kk][tx * 8];
            *(float4*)(rb + 4) = *(const float4*)&Bs[kk][tx * 8 + 4];
#pragma unroll
            for (int i = 0; i < 8; i++)
#pragma unroll
                for (int j = 0; j < 8; j++)
                    acc[i][j] = fmaf(ra[i], rb[j], acc[i][j]);
        }
        __syncthreads();
    }

#pragma unroll
    for (int i = 0; i < 8; i++) {
        int m = bm + ty * 8 + i;
#pragma unroll
        for (int j = 0; j < 8; j += 4) {
            int n = bn + tx * 8 + j;
            float4 r;
            r.x = acc[i][j + 0]; r.y = acc[i][j + 1];
            r.z = acc[i][j + 2]; r.w = acc[i][j + 3];
            if (bias) {
                r.x += bias[n + 0]; r.y += bias[n + 1];
                r.z += bias[n + 2]; r.w += bias[n + 3];
            }
            *(float4*)(C + (size_t)m * N + n) = r;
        }
    }
}

// Fused QKV projection: grid.z selects weight + destination.
__global__ __launch_bounds__(256) void gemm_qkv_kernel(
    const float* __restrict__ X,
    const float* __restrict__ Wq,
    const float* __restrict__ Wk,
    const float* __restrict__ Wv) {
    const float* W = (blockIdx.z == 0) ? Wq : (blockIdx.z == 1) ? Wk : Wv;
    float* C = (blockIdx.z == 0) ? g_Q : (blockIdx.z == 1) ? g_K : g_V;
    gemm_nt_body(X, W, C, nullptr, B_ * S_, D_, D_);
}

// Output projection with bias.
__global__ __launch_bounds__(256) void gemm_out_kernel(
    const float* __restrict__ Wo,
    const float* __restrict__ bo,
    float* __restrict__ out) {
    gemm_nt_body(g_ctx, Wo, out, bo, B_ * S_, D_, D_);
}

// ---------------------------------------------------------------------------
// Flash attention, fp32, causal. One CTA per (b, h, 64-row query tile).
// 256 threads = 16x16, each thread owns a 4x4 of the 64x64 tile.
// smem: Qs[64][64], Kt[64][65] (dim-major), Vs[64][68], Ss[64][65], stats.
// ---------------------------------------------------------------------------
#define QT_ROWS 64
#define ATT_SMEM_FLOATS (64 * 64 + 64 * 65 + 64 * 68 + 64 * 65 + 3 * 64)
#define ATT_SMEM_BYTES  (ATT_SMEM_FLOATS * 4)

__global__ __launch_bounds__(256) void flash_kernel() {
    extern __shared__ float sm[];
    float* Qs  = sm;                    // [64][64]  row-major (q, d)
    float* Kt  = Qs + 64 * 64;          // [64][65]  (d, kseq)  transposed
    float* Vs  = Kt + 64 * 65;          // [64][68]  (kseq, d)
    float* Ss  = Vs + 64 * 68;          // [64][65]  (q, kseq)
    float* m_s = Ss + 64 * 65;          // [64] running max
    float* l_s = m_s + 64;              // [64] running sum
    float* c_s = l_s + 64;              // [64] correction factor

    const int tid = threadIdx.x;
    const int tx  = tid & 15;
    const int ty  = tid >> 4;
    const int qt  = 31 - blockIdx.x;    // heavy tiles first
    const int h   = blockIdx.y;
    const int b   = blockIdx.z;

    const size_t base = (size_t)b * S_ * D_ + (size_t)h * HD_;
    const int q0 = qt * QT_ROWS;

    // Load Q tile (64 rows x 64 dims)
    for (int i = tid; i < 64 * 16; i += 256) {
        int r = i >> 4;
        int v = (i & 15) << 2;
        *(float4*)&Qs[r * 64 + v] =
            *(const float4*)&g_Q[base + (size_t)(q0 + r) * D_ + v];
    }
    if (tid < 64) { m_s[tid] = -CUDART_INF_F; l_s[tid] = 0.f; }

    float o[4][4];
#pragma unroll
    for (int i = 0; i < 4; i++)
#pragma unroll
        for (int j = 0; j < 4; j++) o[i][j] = 0.f;

    __syncthreads();

    for (int kt = 0; kt <= qt; kt++) {
        const int k0 = kt * 64;
        // Load K (transposed into Kt[d][c]) and V (natural [c][d])
        for (int i = tid; i < 64 * 16; i += 256) {
            int r = i >> 4;
            int v = (i & 15) << 2;
            float4 kv = *(const float4*)&g_K[base + (size_t)(k0 + r) * D_ + v];
            Kt[(v + 0) * 65 + r] = kv.x;
            Kt[(v + 1) * 65 + r] = kv.y;
            Kt[(v + 2) * 65 + r] = kv.z;
            Kt[(v + 3) * 65 + r] = kv.w;
            *(float4*)&Vs[r * 68 + v] =
                *(const float4*)&g_V[base + (size_t)(k0 + r) * D_ + v];
        }
        __syncthreads();

        // S = Q K^T  (64x64x64)
        float acc[4][4];
#pragma unroll
        for (int i = 0; i < 4; i++)
#pragma unroll
            for (int j = 0; j < 4; j++) acc[i][j] = 0.f;

#pragma unroll 4
        for (int k = 0; k < 64; k++) {
            float qa[4], kb[4];
#pragma unroll
            for (int i = 0; i < 4; i++) qa[i] = Qs[(ty * 4 + i) * 64 + k];
#pragma unroll
            for (int j = 0; j < 4; j++) kb[j] = Kt[k * 65 + tx * 4 + j];
#pragma unroll
            for (int i = 0; i < 4; i++)
#pragma unroll
                for (int j = 0; j < 4; j++)
                    acc[i][j] = fmaf(qa[i], kb[j], acc[i][j]);
        }

        // Causal mask (before scale, as in reference) + scale 1/sqrt(64)
#pragma unroll
        for (int i = 0; i < 4; i++) {
            int qg = q0 + ty * 4 + i;
#pragma unroll
            for (int j = 0; j < 4; j++) {
                int kg = k0 + tx * 4 + j;
                float s = (kg > qg) ? -CUDART_INF_F : acc[i][j] * 0.125f;
                Ss[(ty * 4 + i) * 65 + tx * 4 + j] = s;
            }
        }
        __syncthreads();

        // Online softmax row update (one thread per row)
        if (tid < 64) {
            const int r = tid;
            float mo = m_s[r];
            float mx = mo;
#pragma unroll 8
            for (int c = 0; c < 64; c++) mx = fmaxf(mx, Ss[r * 65 + c]);
            float corr = __expf(mo - mx);
            float lsum = 0.f;
#pragma unroll 8
            for (int c = 0; c < 64; c++) {
                float p = __expf(Ss[r * 65 + c] - mx);
                Ss[r * 65 + c] = p;
                lsum += p;
            }
            m_s[r] = mx;
            l_s[r] = l_s[r] * corr + lsum;
            c_s[r] = corr;
        }
        __syncthreads();

        // O = diag(corr) O + P V
#pragma unroll
        for (int i = 0; i < 4; i++) {
            float corr = c_s[ty * 4 + i];
#pragma unroll
            for (int j = 0; j < 4; j++) o[i][j] *= corr;
        }
#pragma unroll 4
        for (int k = 0; k < 64; k++) {
            float pv[4];
#pragma unroll
            for (int i = 0; i < 4; i++) pv[i] = Ss[(ty * 4 + i) * 65 + k];
            float4 v4 = *(const float4*)&Vs[k * 68 + tx * 4];
            float vv[4] = {v4.x, v4.y, v4.z, v4.w};
#pragma unroll
            for (int i = 0; i < 4; i++)
#pragma unroll
                for (int j = 0; j < 4; j++)
                    o[i][j] = fmaf(pv[i], vv[j], o[i][j]);
        }
        __syncthreads();
    }

    // Normalize and write ctx (layout (B,S,D) with head offset -> ready for Wo)
#pragma unroll
    for (int i = 0; i < 4; i++) {
        float inv = 1.f / l_s[ty * 4 + i];
        float4 r;
        r.x = o[i][0] * inv; r.y = o[i][1] * inv;
        r.z = o[i][2] * inv; r.w = o[i][3] * inv;
        *(float4*)&g_ctx[base + (size_t)(q0 + ty * 4 + i) * D_ + tx * 4] = r;
    }
}

// ---------------------------------------------------------------------------
extern "C" void kernel_launch(void* const* d_in, const int* in_sizes, int n_in,
                              void* d_out, int out_size) {
    const float* X  = (const float*)d_in[0];
    const float* Wq = (const float*)d_in[1];
    const float* Wk = (const float*)d_in[2];
    const float* Wv = (const float*)d_in[3];
    const float* Wo = (const float*)d_in[4];
    const float* bo = (const float*)d_in[5];
    float* out = (float*)d_out;

    (void)in_sizes; (void)n_in; (void)out_size;

    cudaFuncSetAttribute(flash_kernel,
                         cudaFuncAttributeMaxDynamicSharedMemorySize,
                         ATT_SMEM_BYTES);

    // Phase 1: QKV projections (fused launch)
    {
        dim3 grid(D_ / GBN, (B_ * S_) / GBM, 3);
        gemm_qkv_kernel<<<grid, 256>>>(X, Wq, Wk, Wv);
    }
    // Phase 2: flash attention
    {
        dim3 grid(S_ / QT_ROWS, H_, B_);
        flash_kernel<<<grid, 256, ATT_SMEM_BYTES>>>();
    }
    // Phase 3: output projection + bias
    {
        dim3 grid(D_ / GBN, (B_ * S_) / GBM, 1);
        gemm_out_kernel<<<grid, 256>>>(Wo, bo, out);
    }
}

// round 2
// speedup vs baseline: 1.0060x; 1.0060x over previous
#include <cuda_runtime.h>
#include <math_constants.h>

// ---------------------------------------------------------------------------
// MultiHeadAttention: B=2, S=2048, D=1024, H=16, Hd=64, fp32, causal.
// Phase 1: Q/K/V = X @ W^T        (fused NT-SGEMM, grid.z = {q,k,v})
// Phase 2: flash attention fp32   (per (b,h,qtile) CTA, online softmax)
// Phase 3: out = ctx @ Wo^T + bo  (NT-SGEMM with bias)
// ---------------------------------------------------------------------------

#define B_   2
#define S_   2048
#define D_   1024
#define H_   16
#define HD_  64

#define GBM 128
#define GBN 128
#define GBK 16

// Scratch (allocation-free rule: __device__ globals). 4 x 16 MB.
__device__ float g_Q[B_ * S_ * D_];
__device__ float g_K[B_ * S_ * D_];
__device__ float g_V[B_ * S_ * D_];
__device__ float g_ctx[B_ * S_ * D_];

// ---------------------------------------------------------------------------
// NT SGEMM body: C[M,N] = A[M,K] * B[N,K]^T (+ bias[n])
// 128x128 block tile, BK=16, 256 threads, 8x8 micro-tile per thread.
// ---------------------------------------------------------------------------
__device__ __forceinline__ void gemm_nt_body(const float* __restrict__ A,
                                             const float* __restrict__ Bm,
                                             float* __restrict__ C,
                                             const float* __restrict__ bias,
                                             int M, int N, int K) {
    __shared__ float As[GBK][GBM];
    __shared__ float Bs[GBK][GBN];

    const int tid = threadIdx.x;
    const int tx  = tid & 15;       // 0..15
    const int ty  = tid >> 4;       // 0..15
    const int bm  = blockIdx.y * GBM;
    const int bn  = blockIdx.x * GBN;

    float acc[8][8];
#pragma unroll
    for (int i = 0; i < 8; i++)
#pragma unroll
        for (int j = 0; j < 8; j++) acc[i][j] = 0.f;

    for (int k0 = 0; k0 < K; k0 += GBK) {
        // Load BMxBK of A and BNxBK of B, transposed into smem.
        // 128 rows * 4 float4 per row = 512 float4; 256 threads -> 2 each.
#pragma unroll
        for (int t = 0; t < 2; t++) {
            int idx = tid + t * 256;        // 0..511
            int row = idx >> 2;             // 0..127
            int v   = (idx & 3) << 2;       // 0,4,8,12
            float4 a = *(const float4*)(A + (size_t)(bm + row) * K + k0 + v);
            As[v + 0][row] = a.x; As[v + 1][row] = a.y;
            As[v + 2][row] = a.z; As[v + 3][row] = a.w;
            float4 b = *(const float4*)(Bm + (size_t)(bn + row) * K + k0 + v);
            Bs[v + 0][row] = b.x; Bs[v + 1][row] = b.y;
            Bs[v + 2][row] = b.z; Bs[v + 3][row] = b.w;
        }
        __syncthreads();

#pragma unroll
        for (int kk = 0; kk < GBK; kk++) {
            float ra[8], rb[8];
            *(float4*)(ra)     = *(const float4*)&As[kk][ty * 8];
            *(float4*)(ra + 4) = *(const float4*)&As[kk][ty * 8 + 4];
            *(float4*)(rb)     = *(const float4*)&Bs[kk][tx * 8];
            *(float4*)(rb + 4) = *(const float4*)&Bs[kk][tx * 8 + 4];
#pragma unroll
            for (int i = 0; i < 8; i++)
#pragma unroll
                for (int j = 0; j < 8; j++)
                    acc[i][j] = fmaf(ra[i], rb[j], acc[i][j]);
        }
        __syncthreads();
    }

#pragma unroll
    for (int i = 0; i < 8; i++) {
        int m = bm + ty * 8 + i;
#pragma unroll
        for (int j = 0; j < 8; j += 4) {
            int n = bn + tx * 8 + j;
            float4 r;
            r.x = acc[i][j + 0]; r.y = acc[i][j + 1];
            r.z = acc[i][j + 2]; r.w = acc[i][j + 3];
            if (bias) {
                r.x += bias[n + 0]; r.y += bias[n + 1];
                r.z += bias[n + 2]; r.w += bias[n + 3];
            }
            *(float4*)(C + (size_t)m * N + n) = r;
        }
    }
}

// Fused QKV projection: grid.z selects weight + destination.
__global__ __launch_bounds__(256) void gemm_qkv_kernel(
    const float* __restrict__ X,
    const float* __restrict__ Wq,
    const float* __restrict__ Wk,
    const float* __restrict__ Wv) {
    const float* W = (blockIdx.z == 0) ? Wq : (blockIdx.z == 1) ? Wk : Wv;
    float* C = (blockIdx.z == 0) ? g_Q : (blockIdx.z == 1) ? g_K : g_V;
    gemm_nt_body(X, W, C, nullptr, B_ * S_, D_, D_);
}

// Output projection with bias.
__global__ __launch_bounds__(256) void gemm_out_kernel(
    const float* __restrict__ Wo,
    const float* __restrict__ bo,
    float* __restrict__ out) {
    gemm_nt_body(g_ctx, Wo, out, bo, B_ * S_, D_, D_);
}

// ---------------------------------------------------------------------------
// Flash attention, fp32, causal. One CTA per (b, h, 64-row query tile).
// 256 threads = 16x16, each thread owns a 4x4 of the 64x64 tile.
// smem: Qs[64][64], Kt[64][65] (dim-major), Vs[64][68], Ss[64][65], stats.
// ---------------------------------------------------------------------------
#define QT_ROWS 64
#define ATT_SMEM_FLOATS (64 * 64 + 64 * 65 + 64 * 68 + 64 * 65 + 3 * 64)
#define ATT_SMEM_BYTES  (ATT_SMEM_FLOATS * 4)

__global__ __launch_bounds__(256) void flash_kernel() {
    extern __shared__ float sm[];
    float* Qs  = sm;                    // [64][64]  row-major (q, d)
    float* Kt  = Qs + 64 * 64;          // [64][65]  (d, kseq)  transposed
    float* Vs  = Kt + 64 * 65;          // [64][68]  (kseq, d)
    float* Ss  = Vs + 64 * 68;          // [64][65]  (q, kseq)
    float* m_s = Ss + 64 * 65;          // [64] running max
    float* l_s = m_s + 64;              // [64] running sum
    float* c_s = l_s + 64;              // [64] correction factor

    const int tid = threadIdx.x;
    const int tx  = tid & 15;
    const int ty  = tid >> 4;
    const int qt  = 31 - blockIdx.x;    // heavy tiles first
    const int h   = blockIdx.y;
    const int b   = blockIdx.z;

    const size_t base = (size_t)b * S_ * D_ + (size_t)h * HD_;
    const int q0 = qt * QT_ROWS;

    // Load Q tile (64 rows x 64 dims)
    for (int i = tid; i < 64 * 16; i += 256) {
        int r = i >> 4;
        int v = (i & 15) << 2;
        *(float4*)&Qs[r * 64 + v] =
            *(const float4*)&g_Q[base + (size_t)(q0 + r) * D_ + v];
    }
    if (tid < 64) { m_s[tid] = -CUDART_INF_F; l_s[tid] = 0.f; }

    float o[4][4];
#pragma unroll
    for (int i = 0; i < 4; i++)
#pragma unroll
        for (int j = 0; j < 4; j++) o[i][j] = 0.f;

    __syncthreads();

    for (int kt = 0; kt <= qt; kt++) {
        const int k0 = kt * 64;
        // Load K (transposed into Kt[d][c]) and V (natural [c][d])
        for (int i = tid; i < 64 * 16; i += 256) {
            int r = i >> 4;
            int v = (i & 15) << 2;
            float4 kv = *(const float4*)&g_K[base + (size_t)(k0 + r) * D_ + v];
            Kt[(v + 0) * 65 + r] = kv.x;
            Kt[(v + 1) * 65 + r] = kv.y;
            Kt[(v + 2) * 65 + r] = kv.z;
            Kt[(v + 3) * 65 + r] = kv.w;
            *(float4*)&Vs[r * 68 + v] =
                *(const float4*)&g_V[base + (size_t)(k0 + r) * D_ + v];
        }
        __syncthreads();

        // S = Q K^T  (64x64x64)
        float acc[4][4];
#pragma unroll
        for (int i = 0; i < 4; i++)
#pragma unroll
            for (int j = 0; j < 4; j++) acc[i][j] = 0.f;

#pragma unroll 4
        for (int k = 0; k < 64; k++) {
            float qa[4], kb[4];
#pragma unroll
            for (int i = 0; i < 4; i++) qa[i] = Qs[(ty * 4 + i) * 64 + k];
#pragma unroll
            for (int j = 0; j < 4; j++) kb[j] = Kt[k * 65 + tx * 4 + j];
#pragma unroll
            for (int i = 0; i < 4; i++)
#pragma unroll
                for (int j = 0; j < 4; j++)
                    acc[i][j] = fmaf(qa[i], kb[j], acc[i][j]);
        }

        // Causal mask (before scale, as in reference) + scale 1/sqrt(64)
#pragma unroll
        for (int i = 0; i < 4; i++) {
            int qg = q0 + ty * 4 + i;
#pragma unroll
            for (int j = 0; j < 4; j++) {
                int kg = k0 + tx * 4 + j;
                float s = (kg > qg) ? -CUDART_INF_F : acc[i][j] * 0.125f;
                Ss[(ty * 4 + i) * 65 + tx * 4 + j] = s;
            }
        }
        __syncthreads();

        // Online softmax row update (one thread per row)
        if (tid < 64) {
            const int r = tid;
            float mo = m_s[r];
            float mx = mo;
#pragma unroll 8
            for (int c = 0; c < 64; c++) mx = fmaxf(mx, Ss[r * 65 + c]);
            float corr = __expf(mo - mx);
            float lsum = 0.f;
#pragma unroll 8
            for (int c = 0; c < 64; c++) {
                float p = __expf(Ss[r * 65 + c] - mx);
                Ss[r * 65 + c] = p;
                lsum += p;
            }
            m_s[r] = mx;
            l_s[r] = l_s[r] * corr + lsum;
            c_s[r] = corr;
        }
        __syncthreads();

        // O = diag(corr) O + P V
#pragma unroll
        for (int i = 0; i < 4; i++) {
            float corr = c_s[ty * 4 + i];
#pragma unroll
            for (int j = 0; j < 4; j++) o[i][j] *= corr;
        }
#pragma unroll 4
        for (int k = 0; k < 64; k++) {
            float pv[4];
#pragma unroll
            for (int i = 0; i < 4; i++) pv[i] = Ss[(ty * 4 + i) * 65 + k];
            float4 v4 = *(const float4*)&Vs[k * 68 + tx * 4];
            float vv[4] = {v4.x, v4.y, v4.z, v4.w};
#pragma unroll
            for (int i = 0; i < 4; i++)
#pragma unroll
                for (int j = 0; j < 4; j++)
                    o[i][j] = fmaf(pv[i], vv[j], o[i][j]);
        }
        __syncthreads();
    }

    // Normalize and write ctx (layout (B,S,D) with head offset -> ready for Wo)
#pragma unroll
    for (int i = 0; i < 4; i++) {
        float inv = 1.f / l_s[ty * 4 + i];
        float4 r;
        r.x = o[i][0] * inv; r.y = o[i][1] * inv;
        r.z = o[i][2] * inv; r.w = o[i][3] * inv;
        *(float4*)&g_ctx[base + (size_t)(q0 + ty * 4 + i) * D_ + tx * 4] = r;
    }
}

// ---------------------------------------------------------------------------
extern "C" void kernel_launch(void* const* d_in, const int* in_sizes, int n_in,
                              void* d_out, int out_size) {
    const float* X  = (const float*)d_in[0];
    const float* Wq = (const float*)d_in[1];
    const float* Wk = (const float*)d_in[2];
    const float* Wv = (const float*)d_in[3];
    const float* Wo = (const float*)d_in[4];
    const float* bo = (const float*)d_in[5];
    float* out = (float*)d_out;

    (void)in_sizes; (void)n_in; (void)out_size;

    cudaFuncSetAttribute(flash_kernel,
                         cudaFuncAttributeMaxDynamicSharedMemorySize,
                         ATT_SMEM_BYTES);

    // Phase 1: QKV projections (fused launch)
    {
        dim3 grid(D_ / GBN, (B_ * S_) / GBM, 3);
        gemm_qkv_kernel<<<grid, 256>>>(X, Wq, Wk, Wv);
    }
    // Phase 2: flash attention
    {
        dim3 grid(S_ / QT_ROWS, H_, B_);
        flash_kernel<<<grid, 256, ATT_SMEM_BYTES>>>();
    }
    // Phase 3: output projection + bias
    {
        dim3 grid(D_ / GBN, (B_ * S_) / GBM, 1);
        gemm_out_kernel<<<grid, 256>>>(Wo, bo, out);
    }
}

// round 3
// speedup vs baseline: 3.4235x; 3.4032x over previous
#include <cuda_runtime.h>
#include <math_constants.h>
#include <cstdint>

// ---------------------------------------------------------------------------
// MultiHeadAttention fp32 I/O, tf32 tensor-core compute.
// B=2, S=2048, D=1024, H=16, Hd=64, causal.
//  Phase 1: Q/K/V = X @ W^T    (tf32 NT-GEMM, grid.z selects weight)
//  Phase 2: flash attention    (tf32 mma for QK^T and PV, online softmax)
//  Phase 3: out = ctx @ Wo^T+b (tf32 NT-GEMM)
// ---------------------------------------------------------------------------

#define B_   2
#define S_   2048
#define D_   1024
#define H_   16
#define HD_  64

__device__ float g_Q[B_ * S_ * D_];
__device__ float g_K[B_ * S_ * D_];
__device__ float g_V[B_ * S_ * D_];
__device__ float g_ctx[B_ * S_ * D_];

// --------------------------- helpers ---------------------------------------
__device__ __forceinline__ uint32_t f2tf(float x) {
    uint32_t r;
    asm("cvt.rna.tf32.f32 %0, %1;" : "=r"(r) : "f"(x));
    return r;
}
__device__ __forceinline__ float ex2(float x) {
    float r;
    asm("ex2.approx.ftz.f32 %0, %1;" : "=f"(r) : "f"(x));
    return r;
}
// D(16x8) += A(16x8) * B(8x8); tf32 inputs, fp32 accum.
__device__ __forceinline__ void mma8(float* c, const uint32_t* a, const uint32_t* b) {
    asm volatile(
        "mma.sync.aligned.m16n8k8.row.col.f32.tf32.tf32.f32 "
        "{%0,%1,%2,%3}, {%4,%5,%6,%7}, {%8,%9}, {%0,%1,%2,%3};\n"
        : "+f"(c[0]), "+f"(c[1]), "+f"(c[2]), "+f"(c[3])
        : "r"(a[0]), "r"(a[1]), "r"(a[2]), "r"(a[3]), "r"(b[0]), "r"(b[1]));
}

// ---------------------------------------------------------------------------
// NT tf32 GEMM: C[M,N] = A[M,K] @ B[N,K]^T (+bias). 128x128x32, 256 threads.
// Warp tile 64x32 (4 m-tiles x 4 n-tiles of m16n8k8).
// ---------------------------------------------------------------------------
#define GLDA 36   // 32 + 4 pad

__device__ __forceinline__ void gemm_nt_tf32(const float* __restrict__ A,
                                             const float* __restrict__ Bm,
                                             float* __restrict__ C,
                                             const float* __restrict__ bias,
                                             int M, int N, int K) {
    __shared__ uint32_t As[128 * GLDA];
    __shared__ uint32_t Bs[128 * GLDA];

    const int tid  = threadIdx.x;
    const int warp = tid >> 5;
    const int lane = tid & 31;
    const int g    = lane >> 2;
    const int t    = lane & 3;
    const int wm   = (warp >> 2) * 64;
    const int wn   = (warp & 3) * 32;
    const int bm   = blockIdx.y * 128;
    const int bn   = blockIdx.x * 128;

    const int lrow = tid >> 3;          // +32*i
    const int lc4  = (tid & 7) * 4;

    float acc[4][4][4];
#pragma unroll
    for (int i = 0; i < 4; i++)
#pragma unroll
        for (int j = 0; j < 4; j++)
#pragma unroll
            for (int v = 0; v < 4; v++) acc[i][j][v] = 0.f;

    float4 ra[4], rb[4];
#pragma unroll
    for (int i = 0; i < 4; i++) {
        ra[i] = *(const float4*)(A + (size_t)(bm + lrow + 32 * i) * K + lc4);
        rb[i] = *(const float4*)(Bm + (size_t)(bn + lrow + 32 * i) * K + lc4);
    }

    for (int k0 = 0; k0 < K; k0 += 32) {
#pragma unroll
        for (int i = 0; i < 4; i++) {
            uint4 ua = {f2tf(ra[i].x), f2tf(ra[i].y), f2tf(ra[i].z), f2tf(ra[i].w)};
            *(uint4*)&As[(lrow + 32 * i) * GLDA + lc4] = ua;
            uint4 ub = {f2tf(rb[i].x), f2tf(rb[i].y), f2tf(rb[i].z), f2tf(rb[i].w)};
            *(uint4*)&Bs[(lrow + 32 * i) * GLDA + lc4] = ub;
        }
        __syncthreads();

        if (k0 + 32 < K) {
#pragma unroll
            for (int i = 0; i < 4; i++) {
                ra[i] = *(const float4*)(A + (size_t)(bm + lrow + 32 * i) * K + k0 + 32 + lc4);
                rb[i] = *(const float4*)(Bm + (size_t)(bn + lrow + 32 * i) * K + k0 + 32 + lc4);
            }
        }

#pragma unroll
        for (int kk = 0; kk < 4; kk++) {
            uint32_t af[4][4], bf[4][2];
#pragma unroll
            for (int im = 0; im < 4; im++) {
                int r = wm + 16 * im + g;
                af[im][0] = As[r * GLDA + 8 * kk + t];
                af[im][1] = As[(r + 8) * GLDA + 8 * kk + t];
                af[im][2] = As[r * GLDA + 8 * kk + t + 4];
                af[im][3] = As[(r + 8) * GLDA + 8 * kk + t + 4];
            }
#pragma unroll
            for (int jn = 0; jn < 4; jn++) {
                int r = wn + 8 * jn + g;
                bf[jn][0] = Bs[r * GLDA + 8 * kk + t];
                bf[jn][1] = Bs[r * GLDA + 8 * kk + t + 4];
            }
#pragma unroll
            for (int im = 0; im < 4; im++)
#pragma unroll
                for (int jn = 0; jn < 4; jn++)
                    mma8(acc[im][jn], af[im], bf[jn]);
        }
        __syncthreads();
    }

    // Epilogue: c0(g,2t) c1(g,2t+1) c2(g+8,2t) c3(g+8,2t+1)
#pragma unroll
    for (int im = 0; im < 4; im++) {
        int r0 = bm + wm + 16 * im + g;
#pragma unroll
        for (int jn = 0; jn < 4; jn++) {
            int c0 = bn + wn + 8 * jn + 2 * t;
            float bx = 0.f, by = 0.f;
            if (bias) { bx = bias[c0]; by = bias[c0 + 1]; }
            float2 v0 = {acc[im][jn][0] + bx, acc[im][jn][1] + by};
            float2 v1 = {acc[im][jn][2] + bx, acc[im][jn][3] + by};
            *(float2*)(C + (size_t)r0 * N + c0) = v0;
            *(float2*)(C + (size_t)(r0 + 8) * N + c0) = v1;
        }
    }
}

__global__ __launch_bounds__(256) void gemm_qkv_kernel(
    const float* __restrict__ X, const float* __restrict__ Wq,
    const float* __restrict__ Wk, const float* __restrict__ Wv) {
    const float* W = (blockIdx.z == 0) ? Wq : (blockIdx.z == 1) ? Wk : Wv;
    float* C = (blockIdx.z == 0) ? g_Q : (blockIdx.z == 1) ? g_K : g_V;
    gemm_nt_tf32(X, W, C, nullptr, B_ * S_, D_, D_);
}

__global__ __launch_bounds__(256) void gemm_out_kernel(
    const float* __restrict__ Wo, const float* __restrict__ bo,
    float* __restrict__ out) {
    gemm_nt_tf32(g_ctx, Wo, out, bo, B_ * S_, D_, D_);
}

// ---------------------------------------------------------------------------
// Flash attention, tf32 mma. CTA = (b, h, 128-row q tile); 8 warps.
// Warp owns 16 q-rows (full 64-col key tiles) -> softmax is warp-local.
// smem: Qs[128][68] tf32, Ks[64][68] tf32, Vs[64][72] tf32, Ps[128][68] tf32.
// ---------------------------------------------------------------------------
#define QLD 68
#define VLD 72
#define FL_SMEM_U32 (128 * QLD + 64 * QLD + 64 * VLD + 128 * QLD)
#define FL_SMEM_BYTES (FL_SMEM_U32 * 4)

__global__ __launch_bounds__(256) void flash_kernel() {
    extern __shared__ uint32_t fsm[];
    uint32_t* Qs = fsm;                    // [128][68]
    uint32_t* Ks = Qs + 128 * QLD;         // [64][68]   (key, d)
    uint32_t* Vs = Ks + 64 * QLD;          // [64][72]   (key, d)
    uint32_t* Ps = Vs + 64 * VLD;          // [128][68]

    const int tid  = threadIdx.x;
    const int warp = tid >> 5;
    const int lane = tid & 31;
    const int g    = lane >> 2;
    const int t    = lane & 3;

    const int qt = (int)gridDim.x - 1 - (int)blockIdx.x;   // heavy first
    const int h  = blockIdx.y;
    const int b  = blockIdx.z;
    const int q0 = qt * 128;
    const size_t base = (size_t)b * S_ * D_ + (size_t)h * HD_;

    const int wrow = warp * 16;            // warp's q-row base (local)
    const float SCL = 0.125f * 1.44269504089f; // 1/sqrt(64) * log2(e)

    // Load + cvt Q tile: 128 rows x 64 dims
    {
        const int r0 = tid >> 4;
        const int c4 = (tid & 15) * 4;
#pragma unroll
        for (int i = 0; i < 8; i++) {
            int r = r0 + 16 * i;
            float4 v = *(const float4*)&g_Q[base + (size_t)(q0 + r) * D_ + c4];
            uint4 u = {f2tf(v.x), f2tf(v.y), f2tf(v.z), f2tf(v.w)};
            *(uint4*)&Qs[r * QLD + c4] = u;
        }
    }

    float o[8][4];
#pragma unroll
    for (int nn = 0; nn < 8; nn++)
#pragma unroll
        for (int v = 0; v < 4; v++) o[nn][v] = 0.f;
    float m0 = -CUDART_INF_F, m1 = -CUDART_INF_F;
    float l0 = 0.f, l1 = 0.f;

    __syncthreads();

    const int nkt = 2 * qt + 2;
    for (int kt = 0; kt < nkt; kt++) {
        const int k0 = kt * 64;
        const bool diag = (kt >= 2 * qt);

        // Load + cvt K,V tiles (64x64 each)
        {
            const int r0 = tid >> 4;
            const int c4 = (tid & 15) * 4;
#pragma unroll
            for (int i = 0; i < 4; i++) {
                int r = r0 + 16 * i;
                float4 kv = *(const float4*)&g_K[base + (size_t)(k0 + r) * D_ + c4];
                uint4 uk = {f2tf(kv.x), f2tf(kv.y), f2tf(kv.z), f2tf(kv.w)};
                *(uint4*)&Ks[r * QLD + c4] = uk;
                float4 vv = *(const float4*)&g_V[base + (size_t)(k0 + r) * D_ + c4];
                uint4 uv = {f2tf(vv.x), f2tf(vv.y), f2tf(vv.z), f2tf(vv.w)};
                *(uint4*)&Vs[r * VLD + c4] = uv;
            }
        }
        __syncthreads();

        // S = Q K^T : 16x64 per warp
        float sc[8][4];
#pragma unroll
        for (int nn = 0; nn < 8; nn++)
#pragma unroll
            for (int v = 0; v < 4; v++) sc[nn][v] = 0.f;

#pragma unroll
        for (int kk = 0; kk < 8; kk++) {
            uint32_t qa[4];
            int r = wrow + g;
            qa[0] = Qs[r * QLD + 8 * kk + t];
            qa[1] = Qs[(r + 8) * QLD + 8 * kk + t];
            qa[2] = Qs[r * QLD + 8 * kk + t + 4];
            qa[3] = Qs[(r + 8) * QLD + 8 * kk + t + 4];
#pragma unroll
            for (int nn = 0; nn < 8; nn++) {
                uint32_t kb[2];
                kb[0] = Ks[(8 * nn + g) * QLD + 8 * kk + t];
                kb[1] = Ks[(8 * nn + g) * QLD + 8 * kk + t + 4];
                mma8(sc[nn], qa, kb);
            }
        }

        // scale (+mask) ; rows r0 = q0+wrow+g, r1 = r0+8
        const int gr0 = q0 + wrow + g;
        const int gr1 = gr0 + 8;
        float mx0 = -CUDART_INF_F, mx1 = -CUDART_INF_F;
#pragma unroll
        for (int nn = 0; nn < 8; nn++) {
            int c0 = k0 + 8 * nn + 2 * t;
            float s0 = sc[nn][0] * SCL, s1 = sc[nn][1] * SCL;
            float s2 = sc[nn][2] * SCL, s3 = sc[nn][3] * SCL;
            if (diag) {
                if (c0 > gr0)     s0 = -CUDART_INF_F;
                if (c0 + 1 > gr0) s1 = -CUDART_INF_F;
                if (c0 > gr1)     s2 = -CUDART_INF_F;
                if (c0 + 1 > gr1) s3 = -CUDART_INF_F;
            }
            sc[nn][0] = s0; sc[nn][1] = s1; sc[nn][2] = s2; sc[nn][3] = s3;
            mx0 = fmaxf(mx0, fmaxf(s0, s1));
            mx1 = fmaxf(mx1, fmaxf(s2, s3));
        }
        // quad reduce (lanes of same row: tig 0..3)
        mx0 = fmaxf(mx0, __shfl_xor_sync(0xffffffffu, mx0, 1));
        mx0 = fmaxf(mx0, __shfl_xor_sync(0xffffffffu, mx0, 2));
        mx1 = fmaxf(mx1, __shfl_xor_sync(0xffffffffu, mx1, 1));
        mx1 = fmaxf(mx1, __shfl_xor_sync(0xffffffffu, mx1, 2));

        float mn0 = fmaxf(m0, mx0);
        float mn1 = fmaxf(m1, mx1);
        float corr0 = ex2(m0 - mn0);
        float corr1 = ex2(m1 - mn1);
        m0 = mn0; m1 = mn1;

        float sum0 = 0.f, sum1 = 0.f;
#pragma unroll
        for (int nn = 0; nn < 8; nn++) {
            float p0 = ex2(sc[nn][0] - mn0);
            float p1 = ex2(sc[nn][1] - mn0);
            float p2 = ex2(sc[nn][2] - mn1);
            float p3 = ex2(sc[nn][3] - mn1);
            sum0 += p0 + p1; sum1 += p2 + p3;
            // store P as tf32 for PV mma
            int r = wrow + g;
            Ps[r * QLD + 8 * nn + 2 * t]       = f2tf(p0);
            Ps[r * QLD + 8 * nn + 2 * t + 1]   = f2tf(p1);
            Ps[(r + 8) * QLD + 8 * nn + 2 * t]     = f2tf(p2);
            Ps[(r + 8) * QLD + 8 * nn + 2 * t + 1] = f2tf(p3);
        }
        sum0 += __shfl_xor_sync(0xffffffffu, sum0, 1);
        sum0 += __shfl_xor_sync(0xffffffffu, sum0, 2);
        sum1 += __shfl_xor_sync(0xffffffffu, sum1, 1);
        sum1 += __shfl_xor_sync(0xffffffffu, sum1, 2);
        l0 = l0 * corr0 + sum0;
        l1 = l1 * corr1 + sum1;

#pragma unroll
        for (int nn = 0; nn < 8; nn++) {
            o[nn][0] *= corr0; o[nn][1] *= corr0;
            o[nn][2] *= corr1; o[nn][3] *= corr1;
        }
        __syncwarp();

        // O += P V : A = P[16x64], B = V[64x64]
#pragma unroll
        for (int kk = 0; kk < 8; kk++) {
            uint32_t pa[4];
            int r = wrow + g;
            pa[0] = Ps[r * QLD + 8 * kk + t];
            pa[1] = Ps[(r + 8) * QLD + 8 * kk + t];
            pa[2] = Ps[r * QLD + 8 * kk + t + 4];
            pa[3] = Ps[(r + 8) * QLD + 8 * kk + t + 4];
#pragma unroll
            for (int nn = 0; nn < 8; nn++) {
                uint32_t vb[2];
                vb[0] = Vs[(8 * kk + t) * VLD + 8 * nn + g];
                vb[1] = Vs[(8 * kk + t + 4) * VLD + 8 * nn + g];
                mma8(o[nn], pa, vb);
            }
        }
        __syncthreads();
    }

    // Normalize + store ctx
    const float inv0 = 1.f / l0;
    const float inv1 = 1.f / l1;
    const int gr0 = q0 + wrow + g;
#pragma unroll
    for (int nn = 0; nn < 8; nn++) {
        int c = 8 * nn + 2 * t;
        float2 v0 = {o[nn][0] * inv0, o[nn][1] * inv0};
        float2 v1 = {o[nn][2] * inv1, o[nn][3] * inv1};
        *(float2*)&g_ctx[base + (size_t)gr0 * D_ + c] = v0;
        *(float2*)&g_ctx[base + (size_t)(gr0 + 8) * D_ + c] = v1;
    }
}

// ---------------------------------------------------------------------------
extern "C" void kernel_launch(void* const* d_in, const int* in_sizes, int n_in,
                              void* d_out, int out_size) {
    const float* X  = (const float*)d_in[0];
    const float* Wq = (const float*)d_in[1];
    const float* Wk = (const float*)d_in[2];
    const float* Wv = (const float*)d_in[3];
    const float* Wo = (const float*)d_in[4];
    const float* bo = (const float*)d_in[5];
    float* out = (float*)d_out;
    (void)in_sizes; (void)n_in; (void)out_size;

    cudaFuncSetAttribute(flash_kernel,
                         cudaFuncAttributeMaxDynamicSharedMemorySize,
                         FL_SMEM_BYTES);

    {   // Phase 1: QKV projections
        dim3 grid(D_ / 128, (B_ * S_) / 128, 3);
        gemm_qkv_kernel<<<grid, 256>>>(X, Wq, Wk, Wv);
    }
    {   // Phase 2: flash attention
        dim3 grid(S_ / 128, H_, B_);
        flash_kernel<<<grid, 256, FL_SMEM_BYTES>>>();
    }
    {   // Phase 3: output projection + bias
        dim3 grid(D_ / 128, (B_ * S_) / 128, 1);
        gemm_out_kernel<<<grid, 256>>>(Wo, bo, out);
    }
}

// round 5
// speedup vs baseline: 3.5594x; 1.0397x over previous
#include <cuda_runtime.h>
#include <math_constants.h>
#include <cstdint>

// ---------------------------------------------------------------------------
// MultiHeadAttention fp32 I/O, tf32 tensor-core compute, cp.async pipelines.
// B=2, S=2048, D=1024, H=16, Hd=64, causal.
//  Phase 0: pre-round X and weights to tf32 bit patterns (scratch)
//  Phase 1: Q/K/V = X @ W^T    (tf32 NT-GEMM, epilogue re-rounds to tf32)
//  Phase 2: flash attention    (tf32 mma QK^T / PV, online softmax)
//  Phase 3: out = ctx @ Wo^T+b (tf32 NT-GEMM, fp32 out)
// ---------------------------------------------------------------------------

#define B_   2
#define S_   2048
#define D_   1024
#define H_   16
#define HD_  64

__device__ float g_Q[B_ * S_ * D_];
__device__ float g_K[B_ * S_ * D_];
__device__ float g_V[B_ * S_ * D_];
__device__ float g_ctx[B_ * S_ * D_];
__device__ float g_Xr[B_ * S_ * D_];
__device__ float g_Wqr[D_ * D_];
__device__ float g_Wkr[D_ * D_];
__device__ float g_Wvr[D_ * D_];
__device__ float g_Wor[D_ * D_];

// --------------------------- helpers ---------------------------------------
__device__ __forceinline__ uint32_t f2tf(float x) {
    uint32_t r;
    asm("cvt.rna.tf32.f32 %0, %1;" : "=r"(r) : "f"(x));
    return r;
}
__device__ __forceinline__ float ex2(float x) {
    float r;
    asm("ex2.approx.ftz.f32 %0, %1;" : "=f"(r) : "f"(x));
    return r;
}
__device__ __forceinline__ void mma8(float* c, const uint32_t* a, const uint32_t* b) {
    asm volatile(
        "mma.sync.aligned.m16n8k8.row.col.f32.tf32.tf32.f32 "
        "{%0,%1,%2,%3}, {%4,%5,%6,%7}, {%8,%9}, {%0,%1,%2,%3};\n"
        : "+f"(c[0]), "+f"(c[1]), "+f"(c[2]), "+f"(c[3])
        : "r"(a[0]), "r"(a[1]), "r"(a[2]), "r"(a[3]), "r"(b[0]), "r"(b[1]));
}
__device__ __forceinline__ void cpa16(void* s, const void* g) {
    uint32_t sa = (uint32_t)__cvta_generic_to_shared(s);
    asm volatile("cp.async.cg.shared.global [%0], [%1], 16;" :: "r"(sa), "l"(g));
}
__device__ __forceinline__ void cpa_commit() {
    asm volatile("cp.async.commit_group;");
}
__device__ __forceinline__ void cpa_wait0() {
    asm volatile("cp.async.wait_group 0;");
}

// Phase 0: elementwise tf32 pre-rounding (fp32 bit pattern with rna-rounded
// mantissa), so mma can consume raw loads with zero in-kernel cvt.
__global__ __launch_bounds__(256) void preround_kernel(
    const float* __restrict__ src, float* __restrict__ dst, int n4) {
    int stride = gridDim.x * blockDim.x;
    for (int i = blockIdx.x * blockDim.x + threadIdx.x; i < n4; i += stride) {
        float4 v = *(const float4*)(src + 4 * (size_t)i);
        uint4 u = {f2tf(v.x), f2tf(v.y), f2tf(v.z), f2tf(v.w)};
        *(uint4*)(dst + 4 * (size_t)i) = u;
    }
}

// ---------------------------------------------------------------------------
// NT tf32 GEMM: C[M,N] = A[M,K] @ B[N,K]^T (+bias). 128x128x32, 256 threads,
// 8 warps of 64x32. cp.async 2-stage double buffer, 1 syncthreads per K-step.
// A and Bm must be tf32-pre-rounded. ROUND: round C to tf32 on store.
// ---------------------------------------------------------------------------
#define GLDA 36   // 32 + 4 pad
#define G_STAGE (128 * GLDA)
#define G_SMEM_BYTES (2 * 2 * G_STAGE * 4)

template <bool ROUND, bool BIAS>
__device__ __forceinline__ void gemm_nt_tf32(const float* __restrict__ A,
                                             const float* __restrict__ Bm,
                                             float* __restrict__ C,
                                             const float* __restrict__ bias,
                                             int M, int N, int K) {
    extern __shared__ float gsm[];
    float* As = gsm;                 // [2][128][GLDA]
    float* Bs = gsm + 2 * G_STAGE;   // [2][128][GLDA]

    const int tid  = threadIdx.x;
    const int warp = tid >> 5;
    const int lane = tid & 31;
    const int g    = lane >> 2;
    const int t    = lane & 3;
    const int wm   = (warp >> 2) * 64;
    const int wn   = (warp & 3) * 32;
    const int bm   = blockIdx.y * 128;
    const int bn   = blockIdx.x * 128;

    const int lrow = tid >> 3;          // 0..31 (+32*i)
    const int lc4  = (tid & 7) * 4;

    float acc[4][4][4];
#pragma unroll
    for (int i = 0; i < 4; i++)
#pragma unroll
        for (int j = 0; j < 4; j++)
#pragma unroll
            for (int v = 0; v < 4; v++) acc[i][j][v] = 0.f;

    auto stage_copy = [&](int buf, int k0) {
#pragma unroll
        for (int i = 0; i < 4; i++) {
            int r = lrow + 32 * i;
            cpa16(&As[buf * G_STAGE + r * GLDA + lc4],
                  A + (size_t)(bm + r) * K + k0 + lc4);
            cpa16(&Bs[buf * G_STAGE + r * GLDA + lc4],
                  Bm + (size_t)(bn + r) * K + k0 + lc4);
        }
        cpa_commit();
    };

    const int niter = K / 32;
    stage_copy(0, 0);

    for (int it = 0; it < niter; it++) {
        const int buf = it & 1;
        cpa_wait0();
        __syncthreads();
        if (it + 1 < niter) stage_copy(buf ^ 1, 32 * (it + 1));

        const uint32_t* Au = (const uint32_t*)(As + buf * G_STAGE);
        const uint32_t* Bu = (const uint32_t*)(Bs + buf * G_STAGE);
#pragma unroll
        for (int kk = 0; kk < 4; kk++) {
            uint32_t af[4][4], bf[4][2];
#pragma unroll
            for (int im = 0; im < 4; im++) {
                int r = wm + 16 * im + g;
                af[im][0] = Au[r * GLDA + 8 * kk + t];
                af[im][1] = Au[(r + 8) * GLDA + 8 * kk + t];
                af[im][2] = Au[r * GLDA + 8 * kk + t + 4];
                af[im][3] = Au[(r + 8) * GLDA + 8 * kk + t + 4];
            }
#pragma unroll
            for (int jn = 0; jn < 4; jn++) {
                int r = wn + 8 * jn + g;
                bf[jn][0] = Bu[r * GLDA + 8 * kk + t];
                bf[jn][1] = Bu[r * GLDA + 8 * kk + t + 4];
            }
#pragma unroll
            for (int im = 0; im < 4; im++)
#pragma unroll
                for (int jn = 0; jn < 4; jn++)
                    mma8(acc[im][jn], af[im], bf[jn]);
        }
        __syncthreads();
    }

#pragma unroll
    for (int im = 0; im < 4; im++) {
        int r0 = bm + wm + 16 * im + g;
#pragma unroll
        for (int jn = 0; jn < 4; jn++) {
            int c0 = bn + wn + 8 * jn + 2 * t;
            float v0 = acc[im][jn][0], v1 = acc[im][jn][1];
            float v2 = acc[im][jn][2], v3 = acc[im][jn][3];
            if (BIAS) {
                float bx = bias[c0], by = bias[c0 + 1];
                v0 += bx; v1 += by; v2 += bx; v3 += by;
            }
            if (ROUND) {
                uint2 u0 = {f2tf(v0), f2tf(v1)};
                uint2 u1 = {f2tf(v2), f2tf(v3)};
                *(uint2*)(C + (size_t)r0 * N + c0) = u0;
                *(uint2*)(C + (size_t)(r0 + 8) * N + c0) = u1;
            } else {
                float2 w0 = {v0, v1}, w1 = {v2, v3};
                *(float2*)(C + (size_t)r0 * N + c0) = w0;
                *(float2*)(C + (size_t)(r0 + 8) * N + c0) = w1;
            }
        }
    }
}

__global__ __launch_bounds__(256, 2) void gemm_qkv_kernel() {
    const float* W = (blockIdx.z == 0) ? g_Wqr : (blockIdx.z == 1) ? g_Wkr : g_Wvr;
    float* C = (blockIdx.z == 0) ? g_Q : (blockIdx.z == 1) ? g_K : g_V;
    gemm_nt_tf32<true, false>(g_Xr, W, C, nullptr, B_ * S_, D_, D_);
}

__global__ __launch_bounds__(256, 2) void gemm_out_kernel(
    const float* __restrict__ bo, float* __restrict__ out) {
    gemm_nt_tf32<false, true>(g_ctx, g_Wor, out, bo, B_ * S_, D_, D_);
}

// ---------------------------------------------------------------------------
// Flash attention, tf32 mma. CTA = (b, h, 128-row q tile); 8 warps; warp owns
// 16 q-rows. Q fragments hoisted to registers; P overlays Q smem; K/V tiles
// double-buffered via cp.async.
// ---------------------------------------------------------------------------
#define QLD 68
#define VLD 72
#define FL_SMEM_U32 (128 * QLD + 2 * 64 * QLD + 2 * 64 * VLD)
#define FL_SMEM_BYTES (FL_SMEM_U32 * 4)

__global__ __launch_bounds__(256, 1) void flash_kernel() {
    extern __shared__ uint32_t fsm[];
    uint32_t* Qs = fsm;                       // [128][68], reused as Ps
    uint32_t* Ks = fsm + 128 * QLD;           // [2][64][68]
    uint32_t* Vs = Ks + 2 * 64 * QLD;         // [2][64][72]

    const int tid  = threadIdx.x;
    const int warp = tid >> 5;
    const int lane = tid & 31;
    const int g    = lane >> 2;
    const int t    = lane & 3;

    const int qt = (int)gridDim.x - 1 - (int)blockIdx.x;   // heavy first
    const int h  = blockIdx.y;
    const int b  = blockIdx.z;
    const int q0 = qt * 128;
    const size_t base = (size_t)b * S_ * D_ + (size_t)h * HD_;

    const int wrow = warp * 16;
    const float SCL = 0.125f * 1.44269504089f;  // 1/sqrt(64) * log2(e)

    const int r0l = tid >> 4;          // 0..15
    const int c4  = (tid & 15) * 4;

    auto copy_kv = [&](int buf, int k0) {
#pragma unroll
        for (int i = 0; i < 4; i++) {
            int r = r0l + 16 * i;
            cpa16(&Ks[buf * 64 * QLD + r * QLD + c4],
                  &g_K[base + (size_t)(k0 + r) * D_ + c4]);
            cpa16(&Vs[buf * 64 * VLD + r * VLD + c4],
                  &g_V[base + (size_t)(k0 + r) * D_ + c4]);
        }
        cpa_commit();
    };

    const int nkt = 2 * qt + 2;
    copy_kv(0, 0);

    // Stage Q tile (pre-rounded tf32 bits) into smem
#pragma unroll
    for (int i = 0; i < 8; i++) {
        int r = r0l + 16 * i;
        float4 v = *(const float4*)&g_Q[base + (size_t)(q0 + r) * D_ + c4];
        *(uint4*)&Qs[r * QLD + c4] = *(uint4*)&v;
    }
    __syncthreads();

    // Hoist Q fragments (loop-invariant over key tiles)
    uint32_t qa[8][4];
    {
        const int r = wrow + g;
#pragma unroll
        for (int kk = 0; kk < 8; kk++) {
            qa[kk][0] = Qs[r * QLD + 8 * kk + t];
            qa[kk][1] = Qs[(r + 8) * QLD + 8 * kk + t];
            qa[kk][2] = Qs[r * QLD + 8 * kk + t + 4];
            qa[kk][3] = Qs[(r + 8) * QLD + 8 * kk + t + 4];
        }
    }

    float o[8][4];
#pragma unroll
    for (int nn = 0; nn < 8; nn++)
#pragma unroll
        for (int v = 0; v < 4; v++) o[nn][v] = 0.f;
    float m0 = -CUDART_INF_F, m1 = -CUDART_INF_F;
    float l0 = 0.f, l1 = 0.f;

    for (int kt = 0; kt < nkt; kt++) {
        const int k0 = kt * 64;
        const bool diag = (kt >= 2 * qt);
        const int buf = kt & 1;

        cpa_wait0();
        __syncthreads();
        if (kt + 1 < nkt) copy_kv(buf ^ 1, 64 * (kt + 1));

        const uint32_t* Kb = Ks + buf * 64 * QLD;
        const uint32_t* Vb = Vs + buf * 64 * VLD;

        // S = Q K^T (16x64 per warp)
        float sc[8][4];
#pragma unroll
        for (int nn = 0; nn < 8; nn++)
#pragma unroll
            for (int v = 0; v < 4; v++) sc[nn][v] = 0.f;

#pragma unroll
        for (int kk = 0; kk < 8; kk++) {
#pragma unroll
            for (int nn = 0; nn < 8; nn++) {
                uint32_t kb[2];
                kb[0] = Kb[(8 * nn + g) * QLD + 8 * kk + t];
                kb[1] = Kb[(8 * nn + g) * QLD + 8 * kk + t + 4];
                mma8(sc[nn], qa[kk], kb);
            }
        }

        // mask + scale + row max
        const int gr0 = q0 + wrow + g;
        const int gr1 = gr0 + 8;
        float mx0 = -CUDART_INF_F, mx1 = -CUDART_INF_F;
#pragma unroll
        for (int nn = 0; nn < 8; nn++) {
            int c0 = k0 + 8 * nn + 2 * t;
            float s0 = sc[nn][0] * SCL, s1 = sc[nn][1] * SCL;
            float s2 = sc[nn][2] * SCL, s3 = sc[nn][3] * SCL;
            if (diag) {
                if (c0 > gr0)     s0 = -CUDART_INF_F;
                if (c0 + 1 > gr0) s1 = -CUDART_INF_F;
                if (c0 > gr1)     s2 = -CUDART_INF_F;
                if (c0 + 1 > gr1) s3 = -CUDART_INF_F;
            }
            sc[nn][0] = s0; sc[nn][1] = s1; sc[nn][2] = s2; sc[nn][3] = s3;
            mx0 = fmaxf(mx0, fmaxf(s0, s1));
            mx1 = fmaxf(mx1, fmaxf(s2, s3));
        }
        mx0 = fmaxf(mx0, __shfl_xor_sync(0xffffffffu, mx0, 1));
        mx0 = fmaxf(mx0, __shfl_xor_sync(0xffffffffu, mx0, 2));
        mx1 = fmaxf(mx1, __shfl_xor_sync(0xffffffffu, mx1, 1));
        mx1 = fmaxf(mx1, __shfl_xor_sync(0xffffffffu, mx1, 2));

        float mn0 = fmaxf(m0, mx0);
        float mn1 = fmaxf(m1, mx1);
        float corr0 = ex2(m0 - mn0);
        float corr1 = ex2(m1 - mn1);
        m0 = mn0; m1 = mn1;

        float sum0 = 0.f, sum1 = 0.f;
        {
            const int r = wrow + g;
#pragma unroll
            for (int nn = 0; nn < 8; nn++) {
                float p0 = ex2(sc[nn][0] - mn0);
                float p1 = ex2(sc[nn][1] - mn0);
                float p2 = ex2(sc[nn][2] - mn1);
                float p3 = ex2(sc[nn][3] - mn1);
                sum0 += p0 + p1; sum1 += p2 + p3;
                uint2 u0 = {f2tf(p0), f2tf(p1)};
                uint2 u1 = {f2tf(p2), f2tf(p3)};
                *(uint2*)&Qs[r * QLD + 8 * nn + 2 * t] = u0;
                *(uint2*)&Qs[(r + 8) * QLD + 8 * nn + 2 * t] = u1;
            }
        }
        sum0 += __shfl_xor_sync(0xffffffffu, sum0, 1);
        sum0 += __shfl_xor_sync(0xffffffffu, sum0, 2);
        sum1 += __shfl_xor_sync(0xffffffffu, sum1, 1);
        sum1 += __shfl_xor_sync(0xffffffffu, sum1, 2);
        l0 = l0 * corr0 + sum0;
        l1 = l1 * corr1 + sum1;

#pragma unroll
        for (int nn = 0; nn < 8; nn++) {
            o[nn][0] *= corr0; o[nn][1] *= corr0;
            o[nn][2] *= corr1; o[nn][3] *= corr1;
        }
        __syncwarp();

        // O += P V
#pragma unroll
        for (int kk = 0; kk < 8; kk++) {
            uint32_t pa[4];
            const int r = wrow + g;
            pa[0] = Qs[r * QLD + 8 * kk + t];
            pa[1] = Qs[(r + 8) * QLD + 8 * kk + t];
            pa[2] = Qs[r * QLD + 8 * kk + t + 4];
            pa[3] = Qs[(r + 8) * QLD + 8 * kk + t + 4];
#pragma unroll
            for (int nn = 0; nn < 8; nn++) {
                uint32_t vb[2];
                vb[0] = Vb[(8 * kk + t) * VLD + 8 * nn + g];
                vb[1] = Vb[(8 * kk + t + 4) * VLD + 8 * nn + g];
                mma8(o[nn], pa, vb);
            }
        }
    }

    // Normalize + store ctx rounded to tf32 (feeds out-proj A operand)
    const float inv0 = 1.f / l0;
    const float inv1 = 1.f / l1;
    const int gr0 = q0 + wrow + g;
#pragma unroll
    for (int nn = 0; nn < 8; nn++) {
        int c = 8 * nn + 2 * t;
        uint2 u0 = {f2tf(o[nn][0] * inv0), f2tf(o[nn][1] * inv0)};
        uint2 u1 = {f2tf(o[nn][2] * inv1), f2tf(o[nn][3] * inv1)};
        *(uint2*)&g_ctx[base + (size_t)gr0 * D_ + c] = u0;
        *(uint2*)&g_ctx[base + (size_t)(gr0 + 8) * D_ + c] = u1;
    }
}

// ---------------------------------------------------------------------------
extern "C" void kernel_launch(void* const* d_in, const int* in_sizes, int n_in,
                              void* d_out, int out_size) {
    const float* X  = (const float*)d_in[0];
    const float* Wq = (const float*)d_in[1];
    const float* Wk = (const float*)d_in[2];
    const float* Wv = (const float*)d_in[3];
    const float* Wo = (const float*)d_in[4];
    const float* bo = (const float*)d_in[5];
    float* out = (float*)d_out;
    (void)in_sizes; (void)n_in; (void)out_size;

    static bool attr_done = false;
    if (!attr_done) {
        cudaFuncSetAttribute(flash_kernel,
                             cudaFuncAttributeMaxDynamicSharedMemorySize,
                             FL_SMEM_BYTES);
        cudaFuncSetAttribute(gemm_qkv_kernel,
                             cudaFuncAttributeMaxDynamicSharedMemorySize,
                             G_SMEM_BYTES);
        cudaFuncSetAttribute(gemm_out_kernel,
                             cudaFuncAttributeMaxDynamicSharedMemorySize,
                             G_SMEM_BYTES);
        attr_done = true;
    }

    float* xr;  cudaGetSymbolAddress((void**)&xr,  g_Xr);
    float* wqr; cudaGetSymbolAddress((void**)&wqr, g_Wqr);
    float* wkr; cudaGetSymbolAddress((void**)&wkr, g_Wkr);
    float* wvr; cudaGetSymbolAddress((void**)&wvr, g_Wvr);
    float* wor; cudaGetSymbolAddress((void**)&wor, g_Wor);

    // Phase 0: pre-round operands to tf32 bit patterns
    preround_kernel<<<512, 256>>>(X,  xr,  (B_ * S_ * D_) / 4);
    preround_kernel<<<256, 256>>>(Wq, wqr, (D_ * D_) / 4);
    preround_kernel<<<256, 256>>>(Wk, wkr, (D_ * D_) / 4);
    preround_kernel<<<256, 256>>>(Wv, wvr, (D_ * D_) / 4);
    preround_kernel<<<256, 256>>>(Wo, wor, (D_ * D_) / 4);

    {   // Phase 1: QKV projections
        dim3 grid(D_ / 128, (B_ * S_) / 128, 3);
        gemm_qkv_kernel<<<grid, 256, G_SMEM_BYTES>>>();
    }
    {   // Phase 2: flash attention
        dim3 grid(S_ / 128, H_, B_);
        flash_kernel<<<grid, 256, FL_SMEM_BYTES>>>();
    }
    {   // Phase 3: output projection + bias
        dim3 grid(D_ / 128, (B_ * S_) / 128, 1);
        gemm_out_kernel<<<grid, 256, G_SMEM_BYTES>>>(bo, out);
    }
}

// round 7
// speedup vs baseline: 6.6804x; 1.8769x over previous
#include <cuda_runtime.h>
#include <cuda_fp16.h>
#include <math_constants.h>
#include <cstdint>

// ---------------------------------------------------------------------------
// MultiHeadAttention fp32 I/O, fp16 tensor-core compute (fp32 accumulate).
// B=2, S=2048, D=1024, H=16, Hd=64, causal.
//  Phase 0: convert X and weights to fp16
//  Phase 1: Q/K/V = X @ W^T     (m16n8k16 fp16 GEMM, ldmatrix, cp.async)
//  Phase 2: flash attention      (fp16 mma, P kept in registers, online softmax)
//  Phase 3: out = ctx @ Wo^T + b (fp16 GEMM, fp32 out)
// ---------------------------------------------------------------------------

#define B_   2
#define S_   2048
#define D_   1024
#define H_   16
#define HD_  64

__device__ __half g_Q[B_ * S_ * D_];
__device__ __half g_K[B_ * S_ * D_];
__device__ __half g_V[B_ * S_ * D_];
__device__ __half g_ctx[B_ * S_ * D_];
__device__ __half g_Xh[B_ * S_ * D_];
__device__ __half g_Wqh[D_ * D_];
__device__ __half g_Wkh[D_ * D_];
__device__ __half g_Wvh[D_ * D_];
__device__ __half g_Woh[D_ * D_];

// --------------------------- helpers ---------------------------------------
__device__ __forceinline__ float ex2(float x) {
    float r;
    asm("ex2.approx.ftz.f32 %0, %1;" : "=f"(r) : "f"(x));
    return r;
}
// pack two fp32 -> half2 (lo, hi)
__device__ __forceinline__ uint32_t packh2(float lo, float hi) {
    uint32_t d;
    asm("cvt.rn.f16x2.f32 %0, %1, %2;" : "=r"(d) : "f"(hi), "f"(lo));
    return d;
}
// D(16x8,f32) += A(16x16,f16) * B(16x8,f16)
__device__ __forceinline__ void mma16(float* c, const uint32_t* a, const uint32_t* b) {
    asm volatile(
        "mma.sync.aligned.m16n8k16.row.col.f32.f16.f16.f32 "
        "{%0,%1,%2,%3}, {%4,%5,%6,%7}, {%8,%9}, {%0,%1,%2,%3};\n"
        : "+f"(c[0]), "+f"(c[1]), "+f"(c[2]), "+f"(c[3])
        : "r"(a[0]), "r"(a[1]), "r"(a[2]), "r"(a[3]), "r"(b[0]), "r"(b[1]));
}
__device__ __forceinline__ void ldm_x4(uint32_t* r, uint32_t addr) {
    asm volatile("ldmatrix.sync.aligned.m8n8.x4.shared.b16 {%0,%1,%2,%3}, [%4];"
                 : "=r"(r[0]), "=r"(r[1]), "=r"(r[2]), "=r"(r[3]) : "r"(addr));
}
__device__ __forceinline__ void ldm_x4_t(uint32_t* r, uint32_t addr) {
    asm volatile("ldmatrix.sync.aligned.m8n8.x4.trans.shared.b16 {%0,%1,%2,%3}, [%4];"
                 : "=r"(r[0]), "=r"(r[1]), "=r"(r[2]), "=r"(r[3]) : "r"(addr));
}
__device__ __forceinline__ void cpa16(void* s, const void* g) {
    uint32_t sa = (uint32_t)__cvta_generic_to_shared(s);
    asm volatile("cp.async.cg.shared.global [%0], [%1], 16;" :: "r"(sa), "l"(g));
}
__device__ __forceinline__ void cpa_commit() { asm volatile("cp.async.commit_group;"); }
__device__ __forceinline__ void cpa_wait0()  { asm volatile("cp.async.wait_group 0;"); }
__device__ __forceinline__ uint32_t smem_u32(const void* p) {
    return (uint32_t)__cvta_generic_to_shared(p);
}

// Phase 0: fp32 -> fp16 conversion.
__global__ __launch_bounds__(256) void to_half_kernel(
    const float* __restrict__ src, __half* __restrict__ dst, int n4) {
    int stride = gridDim.x * blockDim.x;
    for (int i = blockIdx.x * blockDim.x + threadIdx.x; i < n4; i += stride) {
        float4 v = *(const float4*)(src + 4 * (size_t)i);
        __half2* d2 = (__half2*)(dst + 4 * (size_t)i);
        d2[0] = __floats2half2_rn(v.x, v.y);
        d2[1] = __floats2half2_rn(v.z, v.w);
    }
}

// ---------------------------------------------------------------------------
// fp16 NT GEMM: C[M,N] = A[M,K] @ B[N,K]^T (+bias). 128x128 block, BK=32,
// 256 threads, 8 warps of 64x32, cp.async double buffer, ldmatrix fragments.
// smem rows padded to 80B (32 halves + 8) -> conflict-free ldmatrix.
// ---------------------------------------------------------------------------
#define GROWB 80                        // bytes per padded smem row
#define G_STG (128 * GROWB)             // 10240 B per tile stage
#define GH_SMEM_BYTES (4 * G_STG)       // A0,A1,B0,B1 = 40960

template <bool HALF_OUT, bool BIAS>
__device__ __forceinline__ void gemm_h(const __half* __restrict__ A,
                                       const __half* __restrict__ Bm,
                                       void* __restrict__ Cv,
                                       const float* __restrict__ bias,
                                       int N, int K) {
    extern __shared__ __align__(128) uint8_t dsm[];
    const int tid  = threadIdx.x;
    const int warp = tid >> 5;
    const int lane = tid & 31;
    const int g    = lane >> 2;
    const int t    = lane & 3;
    const int wm   = (warp >> 2) * 64;
    const int wn   = (warp & 3) * 32;
    const int bm   = blockIdx.y * 128;
    const int bn   = blockIdx.x * 128;

    const uint32_t smb = smem_u32(dsm);

    // ldmatrix lane address components
    const int ar = (lane & 7) + 8 * ((lane >> 3) & 1);  // A row-within-16
    const int am = (lane >> 4);                         // A chunk sel
    const int bmm = lane >> 3;                          // B matrix id
    const int br = ((bmm >> 1) << 3) + (lane & 7);      // B row-within-16
    const int bc = (bmm & 1);                           // B chunk sel

    float acc[4][4][4];
#pragma unroll
    for (int i = 0; i < 4; i++)
#pragma unroll
        for (int j = 0; j < 4; j++)
#pragma unroll
            for (int v = 0; v < 4; v++) acc[i][j][v] = 0.f;

    const int lrow = tid >> 2;          // 0..63 (+64)
    const int lc   = tid & 3;           // chunk 0..3

    auto stage_copy = [&](int buf, int k0) {
#pragma unroll
        for (int i = 0; i < 2; i++) {
            int row = lrow + 64 * i;
            cpa16(dsm + buf * G_STG + row * GROWB + lc * 16,
                  A + (size_t)(bm + row) * K + k0 + lc * 8);
            cpa16(dsm + 2 * G_STG + buf * G_STG + row * GROWB + lc * 16,
                  Bm + (size_t)(bn + row) * K + k0 + lc * 8);
        }
        cpa_commit();
    };

    const int niter = K / 32;
    stage_copy(0, 0);

    for (int it = 0; it < niter; it++) {
        const int buf = it & 1;
        cpa_wait0();
        __syncthreads();
        if (it + 1 < niter) stage_copy(buf ^ 1, 32 * (it + 1));

        const uint32_t Ab = smb + buf * G_STG;
        const uint32_t Bb = smb + 2 * G_STG + buf * G_STG;
#pragma unroll
        for (int kk = 0; kk < 2; kk++) {
            uint32_t af[4][4], bf[4][2];
#pragma unroll
            for (int im = 0; im < 4; im++)
                ldm_x4(af[im], Ab + (wm + 16 * im + ar) * GROWB + (2 * kk + am) * 16);
#pragma unroll
            for (int j2 = 0; j2 < 2; j2++) {
                uint32_t r[4];
                ldm_x4(r, Bb + (wn + 16 * j2 + br) * GROWB + (2 * kk + bc) * 16);
                bf[2 * j2][0] = r[0]; bf[2 * j2][1] = r[1];
                bf[2 * j2 + 1][0] = r[2]; bf[2 * j2 + 1][1] = r[3];
            }
#pragma unroll
            for (int im = 0; im < 4; im++)
#pragma unroll
                for (int jn = 0; jn < 4; jn++)
                    mma16(acc[im][jn], af[im], bf[jn]);
        }
        __syncthreads();
    }

#pragma unroll
    for (int im = 0; im < 4; im++) {
        int r0 = bm + wm + 16 * im + g;
#pragma unroll
        for (int jn = 0; jn < 4; jn++) {
            int c0 = bn + wn + 8 * jn + 2 * t;
            float v0 = acc[im][jn][0], v1 = acc[im][jn][1];
            float v2 = acc[im][jn][2], v3 = acc[im][jn][3];
            if (BIAS) {
                float bx = bias[c0], by = bias[c0 + 1];
                v0 += bx; v1 += by; v2 += bx; v3 += by;
            }
            if (HALF_OUT) {
                __half* C = (__half*)Cv;
                *(__half2*)(C + (size_t)r0 * N + c0) = __floats2half2_rn(v0, v1);
                *(__half2*)(C + (size_t)(r0 + 8) * N + c0) = __floats2half2_rn(v2, v3);
            } else {
                float* C = (float*)Cv;
                float2 w0 = {v0, v1}, w1 = {v2, v3};
                *(float2*)(C + (size_t)r0 * N + c0) = w0;
                *(float2*)(C + (size_t)(r0 + 8) * N + c0) = w1;
            }
        }
    }
}

__global__ __launch_bounds__(256, 2) void gemm_qkv_kernel() {
    const __half* W = (blockIdx.z == 0) ? g_Wqh : (blockIdx.z == 1) ? g_Wkh : g_Wvh;
    __half* C = (blockIdx.z == 0) ? g_Q : (blockIdx.z == 1) ? g_K : g_V;
    gemm_h<true, false>(g_Xh, W, C, nullptr, D_, D_);
}
__global__ __launch_bounds__(256, 2) void gemm_out_kernel(
    const float* __restrict__ bo, float* __restrict__ out) {
    gemm_h<false, true>(g_ctx, g_Woh, out, bo, D_, D_);
}

// ---------------------------------------------------------------------------
// Flash attention, fp16 mma. CTA = (b, h, 128-row q tile); 8 warps; warp owns
// 16 q-rows. Q fragments hoisted; P stays in registers (FA2 layout match);
// K via ldmatrix, V via ldmatrix.trans; K/V double-buffered cp.async.
// smem rows padded to 144B (64 halves + 8).
// ---------------------------------------------------------------------------
#define FROWB 144
#define FQ_BYTES (128 * FROWB)          // 18432
#define FKV_BYTES (64 * FROWB)          // 9216
#define FL_SMEM_BYTES (FQ_BYTES + 4 * FKV_BYTES)   // 55296

__global__ __launch_bounds__(256, 2) void flash_kernel() {
    extern __shared__ __align__(128) uint8_t fsm[];
    uint8_t* Qs = fsm;
    uint8_t* Ks = fsm + FQ_BYTES;
    uint8_t* Vs = fsm + FQ_BYTES + 2 * FKV_BYTES;

    const int tid  = threadIdx.x;
    const int warp = tid >> 5;
    const int lane = tid & 31;
    const int g    = lane >> 2;
    const int t    = lane & 3;

    const int qt = (int)gridDim.x - 1 - (int)blockIdx.x;   // heavy first
    const int h  = blockIdx.y;
    const int b  = blockIdx.z;
    const int q0 = qt * 128;
    const size_t base = (size_t)b * S_ * D_ + (size_t)h * HD_;

    const int wrow = warp * 16;
    const float SCL = 0.125f * 1.44269504089f;  // 1/sqrt(64) * log2(e)

    // ldmatrix lane address components
    const int ar = (lane & 7) + 8 * ((lane >> 3) & 1);  // A row sel
    const int am = (lane >> 4);                         // A chunk sel
    const int bmm = lane >> 3;
    const int br = ((bmm >> 1) << 3) + (lane & 7);      // K(B) row sel
    const int bc = (bmm & 1);                           // K(B) chunk sel
    const int vr = ((bmm & 1) << 3) + (lane & 7);       // V row sel
    const int vc = (bmm >> 1);                          // V chunk sel

    const int krow = tid >> 3;          // 0..31
    const int kc   = tid & 7;           // chunk 0..7

    auto copy_kv = [&](int buf, int k0) {
#pragma unroll
        for (int i = 0; i < 2; i++) {
            int r = krow + 32 * i;
            cpa16(Ks + buf * FKV_BYTES + r * FROWB + kc * 16,
                  g_K + base + (size_t)(k0 + r) * D_ + kc * 8);
            cpa16(Vs + buf * FKV_BYTES + r * FROWB + kc * 16,
                  g_V + base + (size_t)(k0 + r) * D_ + kc * 8);
        }
        cpa_commit();
    };

    const int nkt = 2 * qt + 2;
    copy_kv(0, 0);
    // Q tile via cp.async too
#pragma unroll
    for (int i = 0; i < 4; i++) {
        int r = krow + 32 * i;
        cpa16(Qs + r * FROWB + kc * 16,
              g_Q + base + (size_t)(q0 + r) * D_ + kc * 8);
    }
    cpa_commit();

    const uint32_t Qb32 = smem_u32(Qs);
    cpa_wait0();
    __syncthreads();

    // Hoist Q fragments (A operand, 4 k-steps of 16)
    uint32_t qa[4][4];
#pragma unroll
    for (int kk = 0; kk < 4; kk++)
        ldm_x4(qa[kk], Qb32 + (wrow + ar) * FROWB + (2 * kk + am) * 16);

    float o[8][4];
#pragma unroll
    for (int nn = 0; nn < 8; nn++)
#pragma unroll
        for (int v = 0; v < 4; v++) o[nn][v] = 0.f;
    float m0 = -CUDART_INF_F, m1 = -CUDART_INF_F;
    float l0 = 0.f, l1 = 0.f;

    for (int kt = 0; kt < nkt; kt++) {
        const int k0 = kt * 64;
        const bool diag = (kt >= 2 * qt);
        const int buf = kt & 1;

        if (kt > 0) { cpa_wait0(); __syncthreads(); }
        if (kt + 1 < nkt) copy_kv(buf ^ 1, 64 * (kt + 1));

        const uint32_t Kb = smem_u32(Ks + buf * FKV_BYTES);
        const uint32_t Vb = smem_u32(Vs + buf * FKV_BYTES);

        // S = Q K^T (16x64 per warp)
        float sc[8][4];
#pragma unroll
        for (int nn = 0; nn < 8; nn++)
#pragma unroll
            for (int v = 0; v < 4; v++) sc[nn][v] = 0.f;

#pragma unroll
        for (int kk = 0; kk < 4; kk++) {
#pragma unroll
            for (int j2 = 0; j2 < 4; j2++) {
                uint32_t r[4];
                ldm_x4(r, Kb + (16 * j2 + br) * FROWB + (2 * kk + bc) * 16);
                mma16(sc[2 * j2], qa[kk], &r[0]);
                mma16(sc[2 * j2 + 1], qa[kk], &r[2]);
            }
        }

        // mask + scale + row max
        const int gr0 = q0 + wrow + g;
        const int gr1 = gr0 + 8;
        float mx0 = -CUDART_INF_F, mx1 = -CUDART_INF_F;
#pragma unroll
        for (int nn = 0; nn < 8; nn++) {
            int c0 = k0 + 8 * nn + 2 * t;
            float s0 = sc[nn][0] * SCL, s1 = sc[nn][1] * SCL;
            float s2 = sc[nn][2] * SCL, s3 = sc[nn][3] * SCL;
            if (diag) {
                if (c0 > gr0)     s0 = -CUDART_INF_F;
                if (c0 + 1 > gr0) s1 = -CUDART_INF_F;
                if (c0 > gr1)     s2 = -CUDART_INF_F;
                if (c0 + 1 > gr1) s3 = -CUDART_INF_F;
            }
            sc[nn][0] = s0; sc[nn][1] = s1; sc[nn][2] = s2; sc[nn][3] = s3;
            mx0 = fmaxf(mx0, fmaxf(s0, s1));
            mx1 = fmaxf(mx1, fmaxf(s2, s3));
        }
        mx0 = fmaxf(mx0, __shfl_xor_sync(0xffffffffu, mx0, 1));
        mx0 = fmaxf(mx0, __shfl_xor_sync(0xffffffffu, mx0, 2));
        mx1 = fmaxf(mx1, __shfl_xor_sync(0xffffffffu, mx1, 1));
        mx1 = fmaxf(mx1, __shfl_xor_sync(0xffffffffu, mx1, 2));

        float mn0 = fmaxf(m0, mx0);
        float mn1 = fmaxf(m1, mx1);
        float corr0 = ex2(m0 - mn0);
        float corr1 = ex2(m1 - mn1);
        m0 = mn0; m1 = mn1;

        float sum0 = 0.f, sum1 = 0.f;
#pragma unroll
        for (int nn = 0; nn < 8; nn++) {
            float p0 = ex2(sc[nn][0] - mn0);
            float p1 = ex2(sc[nn][1] - mn0);
            float p2 = ex2(sc[nn][2] - mn1);
            float p3 = ex2(sc[nn][3] - mn1);
            sum0 += p0 + p1; sum1 += p2 + p3;
            sc[nn][0] = p0; sc[nn][1] = p1; sc[nn][2] = p2; sc[nn][3] = p3;
        }
        sum0 += __shfl_xor_sync(0xffffffffu, sum0, 1);
        sum0 += __shfl_xor_sync(0xffffffffu, sum0, 2);
        sum1 += __shfl_xor_sync(0xffffffffu, sum1, 1);
        sum1 += __shfl_xor_sync(0xffffffffu, sum1, 2);
        l0 = l0 * corr0 + sum0;
        l1 = l1 * corr1 + sum1;

#pragma unroll
        for (int nn = 0; nn < 8; nn++) {
            o[nn][0] *= corr0; o[nn][1] *= corr0;
            o[nn][2] *= corr1; o[nn][3] *= corr1;
        }

        // O += P V : P packed straight from registers (FA2 layout match)
#pragma unroll
        for (int kb = 0; kb < 4; kb++) {
            uint32_t pa[4];
            pa[0] = packh2(sc[2 * kb][0],     sc[2 * kb][1]);
            pa[1] = packh2(sc[2 * kb][2],     sc[2 * kb][3]);
            pa[2] = packh2(sc[2 * kb + 1][0], sc[2 * kb + 1][1]);
            pa[3] = packh2(sc[2 * kb + 1][2], sc[2 * kb + 1][3]);
#pragma unroll
            for (int j2 = 0; j2 < 4; j2++) {
                uint32_t r[4];
                ldm_x4_t(r, Vb + (16 * kb + vr) * FROWB + (2 * j2 + vc) * 16);
                mma16(o[2 * j2], pa, &r[0]);
                mma16(o[2 * j2 + 1], pa, &r[2]);
            }
        }
    }

    // Normalize + store ctx (fp16, feeds out-proj)
    const float inv0 = 1.f / l0;
    const float inv1 = 1.f / l1;
    const int gr0 = q0 + wrow + g;
#pragma unroll
    for (int nn = 0; nn < 8; nn++) {
        int c = 8 * nn + 2 * t;
        *(__half2*)&g_ctx[base + (size_t)gr0 * D_ + c] =
            __floats2half2_rn(o[nn][0] * inv0, o[nn][1] * inv0);
        *(__half2*)&g_ctx[base + (size_t)(gr0 + 8) * D_ + c] =
            __floats2half2_rn(o[nn][2] * inv1, o[nn][3] * inv1);
    }
}

// ---------------------------------------------------------------------------
extern "C" void kernel_launch(void* const* d_in, const int* in_sizes, int n_in,
                              void* d_out, int out_size) {
    const float* X  = (const float*)d_in[0];
    const float* Wq = (const float*)d_in[1];
    const float* Wk = (const float*)d_in[2];
    const float* Wv = (const float*)d_in[3];
    const float* Wo = (const float*)d_in[4];
    const float* bo = (const float*)d_in[5];
    float* out = (float*)d_out;
    (void)in_sizes; (void)n_in; (void)out_size;

    static bool attr_done = false;
    if (!attr_done) {
        cudaFuncSetAttribute(flash_kernel,
                             cudaFuncAttributeMaxDynamicSharedMemorySize,
                             FL_SMEM_BYTES);
        cudaFuncSetAttribute(gemm_qkv_kernel,
                             cudaFuncAttributeMaxDynamicSharedMemorySize,
                             GH_SMEM_BYTES);
        cudaFuncSetAttribute(gemm_out_kernel,
                             cudaFuncAttributeMaxDynamicSharedMemorySize,
                             GH_SMEM_BYTES);
        attr_done = true;
    }

    __half* xh;  cudaGetSymbolAddress((void**)&xh,  g_Xh);
    __half* wqh; cudaGetSymbolAddress((void**)&wqh, g_Wqh);
    __half* wkh; cudaGetSymbolAddress((void**)&wkh, g_Wkh);
    __half* wvh; cudaGetSymbolAddress((void**)&wvh, g_Wvh);
    __half* woh; cudaGetSymbolAddress((void**)&woh, g_Woh);

    // Phase 0: fp32 -> fp16 operand conversion
    to_half_kernel<<<512, 256>>>(X,  xh,  (B_ * S_ * D_) / 4);
    to_half_kernel<<<256, 256>>>(Wq, wqh, (D_ * D_) / 4);
    to_half_kernel<<<256, 256>>>(Wk, wkh, (D_ * D_) / 4);
    to_half_kernel<<<256, 256>>>(Wv, wvh, (D_ * D_) / 4);
    to_half_kernel<<<256, 256>>>(Wo, woh, (D_ * D_) / 4);

    {   // Phase 1: QKV projections
        dim3 grid(D_ / 128, (B_ * S_) / 128, 3);
        gemm_qkv_kernel<<<grid, 256, GH_SMEM_BYTES>>>();
    }
    {   // Phase 2: flash attention
        dim3 grid(S_ / 128, H_, B_);
        flash_kernel<<<grid, 256, FL_SMEM_BYTES>>>();
    }
    {   // Phase 3: output projection + bias
        dim3 grid(D_ / 128, (B_ * S_) / 128, 1);
        gemm_out_kernel<<<grid, 256, GH_SMEM_BYTES>>>(bo, out);
    }
}

// round 8
// speedup vs baseline: 7.3692x; 1.1031x over previous
#include <cuda_runtime.h>
#include <cuda_fp16.h>
#include <math_constants.h>
#include <cstdint>

// ---------------------------------------------------------------------------
// MultiHeadAttention fp32 I/O, fp16 tensor-core compute (fp32 accumulate).
// B=2, S=2048, D=1024, H=16, Hd=64, causal.
//  Phase 0: ONE fused convert of X + 4 weights to fp16 (Wq pre-scaled by
//           0.125*log2e so flash softmax needs no scale multiply)
//  Phase 1: Q/K/V = X @ W^T     (m16n8k16 fp16 GEMM, BK=64, ldmatrix, cp.async)
//  Phase 2: flash attention      (fp16 mma, P in registers, online softmax)
//  Phase 3: out = ctx @ Wo^T + b (fp16 GEMM, fp32 out)
// ---------------------------------------------------------------------------

#define B_   2
#define S_   2048
#define D_   1024
#define H_   16
#define HD_  64

__device__ __half g_Q[B_ * S_ * D_];
__device__ __half g_K[B_ * S_ * D_];
__device__ __half g_V[B_ * S_ * D_];
__device__ __half g_ctx[B_ * S_ * D_];
__device__ __half g_Xh[B_ * S_ * D_];
__device__ __half g_Wqh[D_ * D_];
__device__ __half g_Wkh[D_ * D_];
__device__ __half g_Wvh[D_ * D_];
__device__ __half g_Woh[D_ * D_];

// --------------------------- helpers ---------------------------------------
__device__ __forceinline__ float ex2(float x) {
    float r;
    asm("ex2.approx.ftz.f32 %0, %1;" : "=f"(r) : "f"(x));
    return r;
}
__device__ __forceinline__ uint32_t packh2(float lo, float hi) {
    uint32_t d;
    asm("cvt.rn.f16x2.f32 %0, %1, %2;" : "=r"(d) : "f"(hi), "f"(lo));
    return d;
}
__device__ __forceinline__ void mma16(float* c, const uint32_t* a, const uint32_t* b) {
    asm volatile(
        "mma.sync.aligned.m16n8k16.row.col.f32.f16.f16.f32 "
        "{%0,%1,%2,%3}, {%4,%5,%6,%7}, {%8,%9}, {%0,%1,%2,%3};\n"
        : "+f"(c[0]), "+f"(c[1]), "+f"(c[2]), "+f"(c[3])
        : "r"(a[0]), "r"(a[1]), "r"(a[2]), "r"(a[3]), "r"(b[0]), "r"(b[1]));
}
__device__ __forceinline__ void ldm_x4(uint32_t* r, uint32_t addr) {
    asm volatile("ldmatrix.sync.aligned.m8n8.x4.shared.b16 {%0,%1,%2,%3}, [%4];"
                 : "=r"(r[0]), "=r"(r[1]), "=r"(r[2]), "=r"(r[3]) : "r"(addr));
}
__device__ __forceinline__ void ldm_x4_t(uint32_t* r, uint32_t addr) {
    asm volatile("ldmatrix.sync.aligned.m8n8.x4.trans.shared.b16 {%0,%1,%2,%3}, [%4];"
                 : "=r"(r[0]), "=r"(r[1]), "=r"(r[2]), "=r"(r[3]) : "r"(addr));
}
__device__ __forceinline__ void cpa16(void* s, const void* g) {
    uint32_t sa = (uint32_t)__cvta_generic_to_shared(s);
    asm volatile("cp.async.cg.shared.global [%0], [%1], 16;" :: "r"(sa), "l"(g));
}
__device__ __forceinline__ void cpa_commit() { asm volatile("cp.async.commit_group;"); }
__device__ __forceinline__ void cpa_wait0()  { asm volatile("cp.async.wait_group 0;"); }
__device__ __forceinline__ uint32_t smem_u32(const void* p) {
    return (uint32_t)__cvta_generic_to_shared(p);
}

// Phase 0: fused fp32 -> fp16 conversion of all operands; Wq scaled.
#define N4_X ((B_ * S_ * D_) / 4)       // 1048576
#define N4_W ((D_ * D_) / 4)            // 262144
#define SCL_F 0.1803368801111204f        // 0.125 * log2(e)

__global__ __launch_bounds__(256) void to_half_all_kernel(
    const float* __restrict__ X,  const float* __restrict__ Wq,
    const float* __restrict__ Wk, const float* __restrict__ Wv,
    const float* __restrict__ Wo) {
    const int total = N4_X + 4 * N4_W;
    const int stride = gridDim.x * blockDim.x;
    for (int i = blockIdx.x * blockDim.x + threadIdx.x; i < total; i += stride) {
        const float* src;
        __half* dst;
        float scl = 1.f;
        if (i < N4_X) {
            src = X + 4 * (size_t)i;
            dst = g_Xh + 4 * (size_t)i;
        } else {
            int k = i - N4_X;
            int w = k >> 18;            // N4_W == 2^18
            int j = k & (N4_W - 1);
            const float* ws[4] = {Wq, Wk, Wv, Wo};
            __half* ds[4] = {g_Wqh, g_Wkh, g_Wvh, g_Woh};
            src = ws[w] + 4 * (size_t)j;
            dst = ds[w] + 4 * (size_t)j;
            if (w == 0) scl = SCL_F;    // fold softmax scale into Wq
        }
        float4 v = *(const float4*)src;
        __half2* d2 = (__half2*)dst;
        d2[0] = __floats2half2_rn(v.x * scl, v.y * scl);
        d2[1] = __floats2half2_rn(v.z * scl, v.w * scl);
    }
}

// ---------------------------------------------------------------------------
// fp16 NT GEMM: C[M,N] = A[M,K] @ B[N,K]^T (+bias). 128x128 block, BK=64,
// 256 threads, 8 warps of 64x32, cp.async double buffer, ldmatrix fragments.
// smem rows padded to 144B (64 halves + 8 pad halves).
// ---------------------------------------------------------------------------
#define GROWB 144                       // bytes per padded smem row (64h + 8h)
#define G_STG (128 * GROWB)             // 18432 B per tile stage
#define GH_SMEM_BYTES (4 * G_STG)       // A0,A1,B0,B1 = 73728

template <bool HALF_OUT, bool BIAS>
__device__ __forceinline__ void gemm_h(const __half* __restrict__ A,
                                       const __half* __restrict__ Bm,
                                       void* __restrict__ Cv,
                                       const float* __restrict__ bias,
                                       int N, int K) {
    extern __shared__ __align__(128) uint8_t dsm[];
    const int tid  = threadIdx.x;
    const int warp = tid >> 5;
    const int lane = tid & 31;
    const int g    = lane >> 2;
    const int t    = lane & 3;
    const int wm   = (warp >> 2) * 64;
    const int wn   = (warp & 3) * 32;
    const int bm   = blockIdx.y * 128;
    const int bn   = blockIdx.x * 128;

    const uint32_t smb = smem_u32(dsm);

    // ldmatrix lane address components
    const int ar = (lane & 7) + 8 * ((lane >> 3) & 1);  // A row-within-16
    const int am = (lane >> 4);                         // A chunk sel
    const int bmm = lane >> 3;                          // B matrix id
    const int br = ((bmm >> 1) << 3) + (lane & 7);      // B row-within-16
    const int bc = (bmm & 1);                           // B chunk sel

    float acc[4][4][4];
#pragma unroll
    for (int i = 0; i < 4; i++)
#pragma unroll
        for (int j = 0; j < 4; j++)
#pragma unroll
            for (int v = 0; v < 4; v++) acc[i][j][v] = 0.f;

    const int lrow = tid >> 3;          // 0..31 (+32*i)
    const int lc   = tid & 7;           // chunk 0..7

    auto stage_copy = [&](int buf, int k0) {
#pragma unroll
        for (int i = 0; i < 4; i++) {
            int row = lrow + 32 * i;
            cpa16(dsm + buf * G_STG + row * GROWB + lc * 16,
                  A + (size_t)(bm + row) * K + k0 + lc * 8);
            cpa16(dsm + 2 * G_STG + buf * G_STG + row * GROWB + lc * 16,
                  Bm + (size_t)(bn + row) * K + k0 + lc * 8);
        }
        cpa_commit();
    };

    const int niter = K / 64;
    stage_copy(0, 0);

    for (int it = 0; it < niter; it++) {
        const int buf = it & 1;
        cpa_wait0();
        __syncthreads();
        if (it + 1 < niter) stage_copy(buf ^ 1, 64 * (it + 1));

        const uint32_t Ab = smb + buf * G_STG;
        const uint32_t Bb = smb + 2 * G_STG + buf * G_STG;
#pragma unroll
        for (int kk = 0; kk < 4; kk++) {
            uint32_t af[4][4], bf[4][2];
#pragma unroll
            for (int im = 0; im < 4; im++)
                ldm_x4(af[im], Ab + (wm + 16 * im + ar) * GROWB + (2 * kk + am) * 16);
#pragma unroll
            for (int j2 = 0; j2 < 2; j2++) {
                uint32_t r[4];
                ldm_x4(r, Bb + (wn + 16 * j2 + br) * GROWB + (2 * kk + bc) * 16);
                bf[2 * j2][0] = r[0]; bf[2 * j2][1] = r[1];
                bf[2 * j2 + 1][0] = r[2]; bf[2 * j2 + 1][1] = r[3];
            }
#pragma unroll
            for (int im = 0; im < 4; im++)
#pragma unroll
                for (int jn = 0; jn < 4; jn++)
                    mma16(acc[im][jn], af[im], bf[jn]);
        }
        __syncthreads();
    }

#pragma unroll
    for (int im = 0; im < 4; im++) {
        int r0 = bm + wm + 16 * im + g;
#pragma unroll
        for (int jn = 0; jn < 4; jn++) {
            int c0 = bn + wn + 8 * jn + 2 * t;
            float v0 = acc[im][jn][0], v1 = acc[im][jn][1];
            float v2 = acc[im][jn][2], v3 = acc[im][jn][3];
            if (BIAS) {
                float bx = bias[c0], by = bias[c0 + 1];
                v0 += bx; v1 += by; v2 += bx; v3 += by;
            }
            if (HALF_OUT) {
                __half* C = (__half*)Cv;
                *(__half2*)(C + (size_t)r0 * N + c0) = __floats2half2_rn(v0, v1);
                *(__half2*)(C + (size_t)(r0 + 8) * N + c0) = __floats2half2_rn(v2, v3);
            } else {
                float* C = (float*)Cv;
                float2 w0 = {v0, v1}, w1 = {v2, v3};
                *(float2*)(C + (size_t)r0 * N + c0) = w0;
                *(float2*)(C + (size_t)(r0 + 8) * N + c0) = w1;
            }
        }
    }
}

__global__ __launch_bounds__(256, 2) void gemm_qkv_kernel() {
    const __half* W = (blockIdx.z == 0) ? g_Wqh : (blockIdx.z == 1) ? g_Wkh : g_Wvh;
    __half* C = (blockIdx.z == 0) ? g_Q : (blockIdx.z == 1) ? g_K : g_V;
    gemm_h<true, false>(g_Xh, W, C, nullptr, D_, D_);
}
__global__ __launch_bounds__(256, 2) void gemm_out_kernel(
    const float* __restrict__ bo, float* __restrict__ out) {
    gemm_h<false, true>(g_ctx, g_Woh, out, bo, D_, D_);
}

// ---------------------------------------------------------------------------
// Flash attention, fp16 mma. CTA = (b, h, 128-row q tile); 8 warps; warp owns
// 16 q-rows. Q pre-scaled (scale folded into Wq). P stays in registers.
// K via ldmatrix, V via ldmatrix.trans; K/V double-buffered cp.async.
// ---------------------------------------------------------------------------
#define FROWB 144
#define FQ_BYTES (128 * FROWB)          // 18432
#define FKV_BYTES (64 * FROWB)          // 9216
#define FL_SMEM_BYTES (FQ_BYTES + 4 * FKV_BYTES)   // 55296

__global__ __launch_bounds__(256, 2) void flash_kernel() {
    extern __shared__ __align__(128) uint8_t fsm[];
    uint8_t* Qs = fsm;
    uint8_t* Ks = fsm + FQ_BYTES;
    uint8_t* Vs = fsm + FQ_BYTES + 2 * FKV_BYTES;

    const int tid  = threadIdx.x;
    const int warp = tid >> 5;
    const int lane = tid & 31;
    const int g    = lane >> 2;
    const int t    = lane & 3;

    const int qt = (int)gridDim.x - 1 - (int)blockIdx.x;   // heavy first
    const int h  = blockIdx.y;
    const int b  = blockIdx.z;
    const int q0 = qt * 128;
    const size_t base = (size_t)b * S_ * D_ + (size_t)h * HD_;

    const int wrow = warp * 16;

    const int ar = (lane & 7) + 8 * ((lane >> 3) & 1);
    const int am = (lane >> 4);
    const int bmm = lane >> 3;
    const int br = ((bmm >> 1) << 3) + (lane & 7);
    const int bc = (bmm & 1);
    const int vr = ((bmm & 1) << 3) + (lane & 7);
    const int vc = (bmm >> 1);

    const int krow = tid >> 3;
    const int kc   = tid & 7;

    auto copy_kv = [&](int buf, int k0) {
#pragma unroll
        for (int i = 0; i < 2; i++) {
            int r = krow + 32 * i;
            cpa16(Ks + buf * FKV_BYTES + r * FROWB + kc * 16,
                  g_K + base + (size_t)(k0 + r) * D_ + kc * 8);
            cpa16(Vs + buf * FKV_BYTES + r * FROWB + kc * 16,
                  g_V + base + (size_t)(k0 + r) * D_ + kc * 8);
        }
        cpa_commit();
    };

    const int nkt = 2 * qt + 2;
    copy_kv(0, 0);
#pragma unroll
    for (int i = 0; i < 4; i++) {
        int r = krow + 32 * i;
        cpa16(Qs + r * FROWB + kc * 16,
              g_Q + base + (size_t)(q0 + r) * D_ + kc * 8);
    }
    cpa_commit();

    const uint32_t Qb32 = smem_u32(Qs);
    cpa_wait0();
    __syncthreads();

    uint32_t qa[4][4];
#pragma unroll
    for (int kk = 0; kk < 4; kk++)
        ldm_x4(qa[kk], Qb32 + (wrow + ar) * FROWB + (2 * kk + am) * 16);

    float o[8][4];
#pragma unroll
    for (int nn = 0; nn < 8; nn++)
#pragma unroll
        for (int v = 0; v < 4; v++) o[nn][v] = 0.f;
    float m0 = -CUDART_INF_F, m1 = -CUDART_INF_F;
    float l0 = 0.f, l1 = 0.f;

    for (int kt = 0; kt < nkt; kt++) {
        const int k0 = kt * 64;
        const bool diag = (kt >= 2 * qt);
        const int buf = kt & 1;

        if (kt > 0) { cpa_wait0(); __syncthreads(); }
        if (kt + 1 < nkt) copy_kv(buf ^ 1, 64 * (kt + 1));

        const uint32_t Kb = smem_u32(Ks + buf * FKV_BYTES);
        const uint32_t Vb = smem_u32(Vs + buf * FKV_BYTES);

        // S = Q K^T (scores already in log2 domain; scale folded into Q)
        float sc[8][4];
#pragma unroll
        for (int nn = 0; nn < 8; nn++)
#pragma unroll
            for (int v = 0; v < 4; v++) sc[nn][v] = 0.f;

#pragma unroll
        for (int kk = 0; kk < 4; kk++) {
#pragma unroll
            for (int j2 = 0; j2 < 4; j2++) {
                uint32_t r[4];
                ldm_x4(r, Kb + (16 * j2 + br) * FROWB + (2 * kk + bc) * 16);
                mma16(sc[2 * j2], qa[kk], &r[0]);
                mma16(sc[2 * j2 + 1], qa[kk], &r[2]);
            }
        }

        // mask + row max
        const int gr0 = q0 + wrow + g;
        const int gr1 = gr0 + 8;
        float mx0 = -CUDART_INF_F, mx1 = -CUDART_INF_F;
#pragma unroll
        for (int nn = 0; nn < 8; nn++) {
            if (diag) {
                int c0 = k0 + 8 * nn + 2 * t;
                if (c0 > gr0)     sc[nn][0] = -CUDART_INF_F;
                if (c0 + 1 > gr0) sc[nn][1] = -CUDART_INF_F;
                if (c0 > gr1)     sc[nn][2] = -CUDART_INF_F;
                if (c0 + 1 > gr1) sc[nn][3] = -CUDART_INF_F;
            }
            mx0 = fmaxf(mx0, fmaxf(sc[nn][0], sc[nn][1]));
            mx1 = fmaxf(mx1, fmaxf(sc[nn][2], sc[nn][3]));
        }
        mx0 = fmaxf(mx0, __shfl_xor_sync(0xffffffffu, mx0, 1));
        mx0 = fmaxf(mx0, __shfl_xor_sync(0xffffffffu, mx0, 2));
        mx1 = fmaxf(mx1, __shfl_xor_sync(0xffffffffu, mx1, 1));
        mx1 = fmaxf(mx1, __shfl_xor_sync(0xffffffffu, mx1, 2));

        float mn0 = fmaxf(m0, mx0);
        float mn1 = fmaxf(m1, mx1);
        float corr0 = ex2(m0 - mn0);
        float corr1 = ex2(m1 - mn1);
        m0 = mn0; m1 = mn1;

        float sum0 = 0.f, sum1 = 0.f;
#pragma unroll
        for (int nn = 0; nn < 8; nn++) {
            float p0 = ex2(sc[nn][0] - mn0);
            float p1 = ex2(sc[nn][1] - mn0);
            float p2 = ex2(sc[nn][2] - mn1);
            float p3 = ex2(sc[nn][3] - mn1);
            sum0 += p0 + p1; sum1 += p2 + p3;
            sc[nn][0] = p0; sc[nn][1] = p1; sc[nn][2] = p2; sc[nn][3] = p3;
        }
        sum0 += __shfl_xor_sync(0xffffffffu, sum0, 1);
        sum0 += __shfl_xor_sync(0xffffffffu, sum0, 2);
        sum1 += __shfl_xor_sync(0xffffffffu, sum1, 1);
        sum1 += __shfl_xor_sync(0xffffffffu, sum1, 2);
        l0 = l0 * corr0 + sum0;
        l1 = l1 * corr1 + sum1;

#pragma unroll
        for (int nn = 0; nn < 8; nn++) {
            o[nn][0] *= corr0; o[nn][1] *= corr0;
            o[nn][2] *= corr1; o[nn][3] *= corr1;
        }

        // O += P V (P packed straight from registers)
#pragma unroll
        for (int kb = 0; kb < 4; kb++) {
            uint32_t pa[4];
            pa[0] = packh2(sc[2 * kb][0],     sc[2 * kb][1]);
            pa[1] = packh2(sc[2 * kb][2],     sc[2 * kb][3]);
            pa[2] = packh2(sc[2 * kb + 1][0], sc[2 * kb + 1][1]);
            pa[3] = packh2(sc[2 * kb + 1][2], sc[2 * kb + 1][3]);
#pragma unroll
            for (int j2 = 0; j2 < 4; j2++) {
                uint32_t r[4];
                ldm_x4_t(r, Vb + (16 * kb + vr) * FROWB + (2 * j2 + vc) * 16);
                mma16(o[2 * j2], pa, &r[0]);
                mma16(o[2 * j2 + 1], pa, &r[2]);
            }
        }
    }

    // Normalize + store ctx (fp16, feeds out-proj)
    const float inv0 = 1.f / l0;
    const float inv1 = 1.f / l1;
    const int gr0 = q0 + wrow + g;
#pragma unroll
    for (int nn = 0; nn < 8; nn++) {
        int c = 8 * nn + 2 * t;
        *(__half2*)&g_ctx[base + (size_t)gr0 * D_ + c] =
            __floats2half2_rn(o[nn][0] * inv0, o[nn][1] * inv0);
        *(__half2*)&g_ctx[base + (size_t)(gr0 + 8) * D_ + c] =
            __floats2half2_rn(o[nn][2] * inv1, o[nn][3] * inv1);
    }
}

// ---------------------------------------------------------------------------
extern "C" void kernel_launch(void* const* d_in, const int* in_sizes, int n_in,
                              void* d_out, int out_size) {
    const float* X  = (const float*)d_in[0];
    const float* Wq = (const float*)d_in[1];
    const float* Wk = (const float*)d_in[2];
    const float* Wv = (const float*)d_in[3];
    const float* Wo = (const float*)d_in[4];
    const float* bo = (const float*)d_in[5];
    float* out = (float*)d_out;
    (void)in_sizes; (void)n_in; (void)out_size;

    static bool attr_done = false;
    if (!attr_done) {
        cudaFuncSetAttribute(flash_kernel,
                             cudaFuncAttributeMaxDynamicSharedMemorySize,
                             FL_SMEM_BYTES);
        cudaFuncSetAttribute(gemm_qkv_kernel,
                             cudaFuncAttributeMaxDynamicSharedMemorySize,
                             GH_SMEM_BYTES);
        cudaFuncSetAttribute(gemm_out_kernel,
                             cudaFuncAttributeMaxDynamicSharedMemorySize,
                             GH_SMEM_BYTES);
        attr_done = true;
    }

    // Phase 0: one fused conversion launch (Wq pre-scaled by 0.125*log2e)
    to_half_all_kernel<<<592, 256>>>(X, Wq, Wk, Wv, Wo);

    {   // Phase 1: QKV projections
        dim3 grid(D_ / 128, (B_ * S_) / 128, 3);
        gemm_qkv_kernel<<<grid, 256, GH_SMEM_BYTES>>>();
    }
    {   // Phase 2: flash attention
        dim3 grid(S_ / 128, H_, B_);
        flash_kernel<<<grid, 256, FL_SMEM_BYTES>>>();
    }
    {   // Phase 3: output projection + bias
        dim3 grid(D_ / 128, (B_ * S_) / 128, 1);
        gemm_out_kernel<<<grid, 256, GH_SMEM_BYTES>>>(bo, out);
    }
}